// round 4
// baseline (speedup 1.0000x reference)
#include <cuda_runtime.h>
#include <math.h>
#include <stdint.h>

#define BATCH 2
#define SEQ 2048
#define DMODEL 1024
#define HEADS 16
#define DK 64
#define NROWS (BATCH*HEADS*SEQ)
#define NTILES 16

// tf32-rounded copies of inputs
static __device__ float g_cq[BATCH*SEQ*DMODEL];
static __device__ float g_ck[BATCH*SEQ*DMODEL];
static __device__ float g_cv[BATCH*SEQ*DMODEL];
static __device__ float g_cwq[DMODEL*DMODEL];
static __device__ float g_cwk[DMODEL*DMODEL];
static __device__ float g_cwv[DMODEL*DMODEL];
static __device__ float g_cwo[DMODEL*DMODEL];
// Projected scratch (tf32-rounded), [B,S,D] layout
static __device__ float g_q[BATCH*SEQ*DMODEL];
static __device__ float g_k[BATCH*SEQ*DMODEL];
static __device__ float g_v[BATCH*SEQ*DMODEL];
static __device__ float g_ctx[BATCH*SEQ*DMODEL];
// softmax stats
static __device__ float g_pmax[NROWS*NTILES];
static __device__ float g_psum[NROWS*NTILES];
static __device__ float g_m[NROWS];
static __device__ float g_inv[NROWS];

__device__ __forceinline__ float to_tf32(float x) {
    float y;
    asm("cvt.rna.tf32.f32 %0, %1;" : "=f"(y) : "f"(x));
    return y;
}
__device__ __forceinline__ void mma8(float* d, const uint32_t* a, const uint32_t* b) {
    asm volatile(
        "mma.sync.aligned.m16n8k8.row.col.f32.tf32.tf32.f32 "
        "{%0,%1,%2,%3}, {%4,%5,%6,%7}, {%8,%9}, {%0,%1,%2,%3};\n"
        : "+f"(d[0]), "+f"(d[1]), "+f"(d[2]), "+f"(d[3])
        : "r"(a[0]), "r"(a[1]), "r"(a[2]), "r"(a[3]),
          "r"(b[0]), "r"(b[1]));
}
__device__ __forceinline__ void cp16(uint32_t dst_smem, const void* src) {
    asm volatile("cp.async.cg.shared.global [%0], [%1], 16;\n" :: "r"(dst_smem), "l"(src));
}
__device__ __forceinline__ void cp_commit() { asm volatile("cp.async.commit_group;\n"); }
template<int N> __device__ __forceinline__ void cp_wait() {
    asm volatile("cp.async.wait_group %0;\n" :: "n"(N));
}

// ---------------------------------------------------------------------------
// tf32 conversion pre-pass: z selects one of up to 4 (src,dst,n4) triples.
// ---------------------------------------------------------------------------
__global__ void __launch_bounds__(256)
cvt_pass(const float* s0, float* d0, int n0,
         const float* s1, float* d1, int n1,
         const float* s2, float* d2, int n2,
         const float* s3, float* d3, int n3)
{
    const int z = blockIdx.y;
    const float* s = (z==0)?s0:((z==1)?s1:((z==2)?s2:s3));
    float*       d = (z==0)?d0:((z==1)?d1:((z==2)?d2:d3));
    const int    n = (z==0)?n0:((z==1)?n1:((z==2)?n2:n3));  // in float4s
    for (int i = blockIdx.x*256 + threadIdx.x; i < n; i += gridDim.x*256) {
        float4 x = ((const float4*)s)[i];
        x.x = to_tf32(x.x); x.y = to_tf32(x.y);
        x.z = to_tf32(x.z); x.w = to_tf32(x.w);
        ((float4*)d)[i] = x;
    }
}

// ---------------------------------------------------------------------------
// Projection GEMM: C[4096,1024] = A @ W^T + bias, z selects triple.
// Inputs pre-rounded to tf32 -> raw fragment loads. CVT_OUT: round result.
// ---------------------------------------------------------------------------
template<bool CVT_OUT>
__global__ void __launch_bounds__(256, 2)
proj_gemm(const float* __restrict__ A0, const float* __restrict__ A1, const float* __restrict__ A2,
          const float* __restrict__ W0, const float* __restrict__ W1, const float* __restrict__ W2,
          const float* __restrict__ B0, const float* __restrict__ B1, const float* __restrict__ B2,
          float* __restrict__ C0, float* __restrict__ C1, float* __restrict__ C2)
{
    extern __shared__ __align__(16) float sm[];
    const int tid = threadIdx.x;
    const int z = blockIdx.z;
    const float* A    = (z==0) ? A0 : ((z==1) ? A1 : A2);
    const float* W    = (z==0) ? W0 : ((z==1) ? W1 : W2);
    const float* bias = (z==0) ? B0 : ((z==1) ? B1 : B2);
    float*       C    = (z==0) ? C0 : ((z==1) ? C1 : C2);
    const int tileN = blockIdx.x * 128;
    const int tileM = blockIdx.y * 128;

    const int warp = tid >> 5, lane = tid & 31, gid = lane >> 2, tig = lane & 3;
    const int wM = (warp & 1) * 64, wN = (warp >> 1) * 32;
    const uint32_t smb = (uint32_t)__cvta_generic_to_shared(sm);

    float acc[4][4][4];
    #pragma unroll
    for (int i=0;i<4;++i)
        #pragma unroll
        for (int j=0;j<4;++j)
            #pragma unroll
            for (int r=0;r<4;++r) acc[i][j][r]=0.f;

    #pragma unroll
    for (int i=0;i<4;++i) {
        int e = tid + i*256, m = e>>3, kq = e&7;
        cp16(smb + (uint32_t)((m*36 + kq*4)*4),          A + (size_t)(tileM+m)*1024 + kq*4);
        cp16(smb + (uint32_t)((9216 + m*36 + kq*4)*4),   W + (size_t)(tileN+m)*1024 + kq*4);
    }
    cp_commit();

    for (int it = 0; it < 32; ++it) {
        const int cur = it & 1;
        if (it < 31) {
            const int nb = cur ^ 1;
            const int k0 = (it+1)*32;
            #pragma unroll
            for (int i=0;i<4;++i) {
                int e = tid + i*256, m = e>>3, kq = e&7;
                cp16(smb + (uint32_t)((nb*4608 + m*36 + kq*4)*4),        A + (size_t)(tileM+m)*1024 + k0 + kq*4);
                cp16(smb + (uint32_t)((9216 + nb*4608 + m*36 + kq*4)*4), W + (size_t)(tileN+m)*1024 + k0 + kq*4);
            }
            cp_commit();
            cp_wait<1>();
        } else {
            cp_wait<0>();
        }
        __syncthreads();

        const float* As = sm + cur*4608;
        const float* Ws = sm + 9216 + cur*4608;
        #pragma unroll
        for (int ks = 0; ks < 32; ks += 8) {
            uint32_t af[4][4], bf[4][2];
            #pragma unroll
            for (int mi=0;mi<4;++mi) {
                const int m0 = wM + mi*16;
                af[mi][0] = __float_as_uint(As[(m0+gid  )*36 + ks+tig  ]);
                af[mi][1] = __float_as_uint(As[(m0+gid+8)*36 + ks+tig  ]);
                af[mi][2] = __float_as_uint(As[(m0+gid  )*36 + ks+tig+4]);
                af[mi][3] = __float_as_uint(As[(m0+gid+8)*36 + ks+tig+4]);
            }
            #pragma unroll
            for (int ni=0;ni<4;++ni) {
                const int n0 = wN + ni*8;
                bf[ni][0] = __float_as_uint(Ws[(n0+gid)*36 + ks+tig  ]);
                bf[ni][1] = __float_as_uint(Ws[(n0+gid)*36 + ks+tig+4]);
            }
            #pragma unroll
            for (int mi=0;mi<4;++mi)
                #pragma unroll
                for (int ni=0;ni<4;++ni)
                    mma8(acc[mi][ni], af[mi], bf[ni]);
        }
        __syncthreads();
    }

    #pragma unroll
    for (int mi=0;mi<4;++mi) {
        const int r0 = tileM + wM + mi*16 + gid;
        #pragma unroll
        for (int ni=0;ni<4;++ni) {
            const int c0 = tileN + wN + ni*8 + tig*2;
            const float b0 = bias[c0], b1 = bias[c0+1];
            float v0 = acc[mi][ni][0]+b0, v1 = acc[mi][ni][1]+b1;
            float v2 = acc[mi][ni][2]+b0, v3 = acc[mi][ni][3]+b1;
            if (CVT_OUT) {
                v0 = to_tf32(v0); v1 = to_tf32(v1);
                v2 = to_tf32(v2); v3 = to_tf32(v3);
            }
            *(float2*)(C + (size_t)r0*1024 + c0)     = make_float2(v0, v1);
            *(float2*)(C + (size_t)(r0+8)*1024 + c0) = make_float2(v2, v3);
        }
    }
}

// ---------------------------------------------------------------------------
// Scores + per-tile row stats (q,k pre-rounded tf32 -> raw loads).
// ---------------------------------------------------------------------------
__global__ void __launch_bounds__(256, 2)
scores_stats(const float* __restrict__ q, const float* __restrict__ kmat,
             float* __restrict__ probs, float* __restrict__ pmax, float* __restrict__ psum)
{
    extern __shared__ __align__(16) float sm[];
    const int tid = threadIdx.x;
    const int ntile = blockIdx.x, rowtile = blockIdx.y, z = blockIdx.z;
    const int b = z >> 4, h = z & 15;

    const float* Qp = q    + ((size_t)b*SEQ + rowtile*128)*DMODEL + h*DK;
    const float* Kp = kmat + ((size_t)b*SEQ + ntile*128)*DMODEL + h*DK;
    const uint32_t smb = (uint32_t)__cvta_generic_to_shared(sm);

    #pragma unroll
    for (int i=0;i<8;++i) {
        int e = tid + i*256, m = e>>4, kq = e&15;
        cp16(smb + (uint32_t)((m*68 + kq*4)*4),          Qp + (size_t)m*1024 + kq*4);
        cp16(smb + (uint32_t)((8704 + m*68 + kq*4)*4),   Kp + (size_t)m*1024 + kq*4);
    }
    cp_commit(); cp_wait<0>();
    __syncthreads();

    const int warp = tid >> 5, lane = tid & 31, gid = lane >> 2, tig = lane & 3;
    const int wM = (warp & 1) * 64, wN = (warp >> 1) * 32, warp_n = warp >> 1;

    float acc[4][4][4];
    #pragma unroll
    for (int i=0;i<4;++i)
        #pragma unroll
        for (int j=0;j<4;++j)
            #pragma unroll
            for (int r=0;r<4;++r) acc[i][j][r]=0.f;

    const float* Qs = sm;
    const float* Ks = sm + 8704;
    #pragma unroll
    for (int ks = 0; ks < 64; ks += 8) {
        uint32_t af[4][4], bf[4][2];
        #pragma unroll
        for (int mi=0;mi<4;++mi) {
            const int m0 = wM + mi*16;
            af[mi][0] = __float_as_uint(Qs[(m0+gid  )*68 + ks+tig  ]);
            af[mi][1] = __float_as_uint(Qs[(m0+gid+8)*68 + ks+tig  ]);
            af[mi][2] = __float_as_uint(Qs[(m0+gid  )*68 + ks+tig+4]);
            af[mi][3] = __float_as_uint(Qs[(m0+gid+8)*68 + ks+tig+4]);
        }
        #pragma unroll
        for (int ni=0;ni<4;++ni) {
            const int n0 = wN + ni*8;
            bf[ni][0] = __float_as_uint(Ks[(n0+gid)*68 + ks+tig  ]);
            bf[ni][1] = __float_as_uint(Ks[(n0+gid)*68 + ks+tig+4]);
        }
        #pragma unroll
        for (int mi=0;mi<4;++mi)
            #pragma unroll
            for (int ni=0;ni<4;++ni)
                mma8(acc[mi][ni], af[mi], bf[ni]);
    }

    #pragma unroll
    for (int mi=0;mi<4;++mi)
        #pragma unroll
        for (int ni=0;ni<4;++ni)
            #pragma unroll
            for (int r=0;r<4;++r) acc[mi][ni][r] *= 0.125f;

    float rm[4][2], rs[4][2];
    #pragma unroll
    for (int mi=0;mi<4;++mi) {
        #pragma unroll
        for (int hf=0;hf<2;++hf) {
            float mx = -1e30f;
            #pragma unroll
            for (int ni=0;ni<4;++ni)
                mx = fmaxf(mx, fmaxf(acc[mi][ni][hf*2], acc[mi][ni][hf*2+1]));
            mx = fmaxf(mx, __shfl_xor_sync(0xffffffffu, mx, 1));
            mx = fmaxf(mx, __shfl_xor_sync(0xffffffffu, mx, 2));
            float s = 0.f;
            #pragma unroll
            for (int ni=0;ni<4;++ni) {
                s += __expf(acc[mi][ni][hf*2]   - mx);
                s += __expf(acc[mi][ni][hf*2+1] - mx);
            }
            s += __shfl_xor_sync(0xffffffffu, s, 1);
            s += __shfl_xor_sync(0xffffffffu, s, 2);
            rm[mi][hf] = mx; rs[mi][hf] = s;
        }
    }
    __syncthreads();
    float2* red = (float2*)sm;
    if (tig == 0) {
        #pragma unroll
        for (int mi=0;mi<4;++mi)
            #pragma unroll
            for (int hf=0;hf<2;++hf) {
                const int row = wM + mi*16 + gid + hf*8;
                red[warp_n*128 + row] = make_float2(rm[mi][hf], rs[mi][hf]);
            }
    }
    __syncthreads();
    if (tid < 128) {
        float2 p0 = red[tid], p1 = red[128+tid], p2 = red[256+tid], p3 = red[384+tid];
        float M = fmaxf(fmaxf(p0.x, p1.x), fmaxf(p2.x, p3.x));
        float S = p0.y*__expf(p0.x-M) + p1.y*__expf(p1.x-M)
                + p2.y*__expf(p2.x-M) + p3.y*__expf(p3.x-M);
        const size_t grow = (size_t)z*SEQ + rowtile*128 + tid;
        pmax[grow*NTILES + ntile] = M;
        psum[grow*NTILES + ntile] = S;
    }

    float* Cp = probs + (size_t)z*SEQ*SEQ;
    #pragma unroll
    for (int mi=0;mi<4;++mi) {
        const int r0 = rowtile*128 + wM + mi*16 + gid;
        #pragma unroll
        for (int ni=0;ni<4;++ni) {
            const int c0 = ntile*128 + wN + ni*8 + tig*2;
            *(float2*)(Cp + (size_t)r0*SEQ + c0)     = make_float2(acc[mi][ni][0], acc[mi][ni][1]);
            *(float2*)(Cp + (size_t)(r0+8)*SEQ + c0) = make_float2(acc[mi][ni][2], acc[mi][ni][3]);
        }
    }
}

__global__ void __launch_bounds__(256)
reduce_stats(const float* __restrict__ pmax, const float* __restrict__ psum,
             float* __restrict__ gm, float* __restrict__ ginv)
{
    const int r = blockIdx.x * 256 + threadIdx.x;
    float mx[NTILES], sx[NTILES];
    #pragma unroll
    for (int t=0;t<NTILES;++t) { mx[t]=pmax[(size_t)r*NTILES+t]; sx[t]=psum[(size_t)r*NTILES+t]; }
    float M = -1e30f;
    #pragma unroll
    for (int t=0;t<NTILES;++t) M = fmaxf(M, mx[t]);
    float S = 0.f;
    #pragma unroll
    for (int t=0;t<NTILES;++t) S += sx[t]*__expf(mx[t]-M);
    gm[r] = M; ginv[r] = 1.f/S;
}

// ---------------------------------------------------------------------------
// Fused normalize + ctx (v pre-rounded tf32 -> raw B loads; Ps stored tf32).
// ctx written tf32-rounded so outproj loads raw.
// ---------------------------------------------------------------------------
__global__ void __launch_bounds__(256, 2)
norm_ctx(float* __restrict__ probs, const float* __restrict__ v,
         const float* __restrict__ gm, const float* __restrict__ ginv,
         float* __restrict__ ctx)
{
    extern __shared__ __align__(16) float sm[];
    float* Ps  = sm;
    float* Vs  = sm + 16896;
    float* smm = sm + 26112;
    float* smi = sm + 26240;

    const int tid = threadIdx.x, rowtile = blockIdx.x, z = blockIdx.y;
    const int b = z >> 4, h = z & 15;
    const size_t grow0 = (size_t)z*SEQ + rowtile*128;
    if (tid < 128) { smm[tid] = gm[grow0+tid]; smi[tid] = ginv[grow0+tid]; }

    const int warp = tid >> 5, lane = tid & 31, gid = lane >> 2, tig = lane & 3;
    const int m0 = warp * 16;
    const uint32_t smb = (uint32_t)__cvta_generic_to_shared(sm);

    const float* Vp0 = v + (size_t)b*SEQ*DMODEL + h*DK;
    float* P0 = probs + (size_t)z*SEQ*SEQ + (size_t)(rowtile*128)*SEQ;

    float acc[8][4];
    #pragma unroll
    for (int i=0;i<8;++i)
        #pragma unroll
        for (int r=0;r<4;++r) acc[i][r]=0.f;

    __syncthreads();

    for (int nt = 0; nt < 16; ++nt) {
        #pragma unroll
        for (int i=0;i<8;++i) {
            int e = tid + i*256, r = e>>4, kq = e&15;
            cp16(smb + (uint32_t)((16896 + r*72 + kq*4)*4),
                 Vp0 + (size_t)(nt*128+r)*1024 + kq*4);
        }
        cp_commit();

        #pragma unroll 4
        for (int j=0;j<16;++j) {
            const int e = tid + j*256, row = e>>5, c4 = e&31;
            float4* gp = (float4*)(P0 + (size_t)row*SEQ + nt*128 + c4*4);
            float4 x = *gp;
            const float M = smm[row], IV = smi[row];
            x.x = __expf(x.x - M)*IV;
            x.y = __expf(x.y - M)*IV;
            x.z = __expf(x.z - M)*IV;
            x.w = __expf(x.w - M)*IV;
            *gp = x;
            float4 t;
            t.x = to_tf32(x.x); t.y = to_tf32(x.y);
            t.z = to_tf32(x.z); t.w = to_tf32(x.w);
            *(float4*)(Ps + row*132 + c4*4) = t;
        }
        cp_wait<0>();
        __syncthreads();

        #pragma unroll 4
        for (int ks = 0; ks < 128; ks += 8) {
            uint32_t af[4], bf[8][2];
            af[0] = __float_as_uint(Ps[(m0+gid  )*132 + ks+tig  ]);
            af[1] = __float_as_uint(Ps[(m0+gid+8)*132 + ks+tig  ]);
            af[2] = __float_as_uint(Ps[(m0+gid  )*132 + ks+tig+4]);
            af[3] = __float_as_uint(Ps[(m0+gid+8)*132 + ks+tig+4]);
            #pragma unroll
            for (int ni=0;ni<8;++ni) {
                const int n0 = ni*8;
                bf[ni][0] = __float_as_uint(Vs[(ks+tig  )*72 + n0+gid]);
                bf[ni][1] = __float_as_uint(Vs[(ks+tig+4)*72 + n0+gid]);
            }
            #pragma unroll
            for (int ni=0;ni<8;++ni)
                mma8(acc[ni], af, bf[ni]);
        }
        __syncthreads();
    }

    float* Cp = ctx + ((size_t)b*SEQ + rowtile*128)*DMODEL + h*DK;
    #pragma unroll
    for (int ni=0;ni<8;++ni) {
        const int c0 = ni*8 + tig*2;
        *(float2*)(Cp + (size_t)(m0+gid)*1024 + c0)
            = make_float2(to_tf32(acc[ni][0]), to_tf32(acc[ni][1]));
        *(float2*)(Cp + (size_t)(m0+gid+8)*1024 + c0)
            = make_float2(to_tf32(acc[ni][2]), to_tf32(acc[ni][3]));
    }
}

// ---------------------------------------------------------------------------
extern "C" void kernel_launch(void* const* d_in, const int* in_sizes, int n_in,
                              void* d_out, int out_size)
{
    const float* Q  = (const float*)d_in[0];
    const float* K_ = (const float*)d_in[1];
    const float* V  = (const float*)d_in[2];
    const float* Wq = (const float*)d_in[3];
    const float* bq = (const float*)d_in[4];
    const float* Wk = (const float*)d_in[5];
    const float* bk = (const float*)d_in[6];
    const float* Wv = (const float*)d_in[7];
    const float* bv = (const float*)d_in[8];
    const float* Wo = (const float*)d_in[9];
    const float* bo = (const float*)d_in[10];

    float* probs = (float*)d_out;
    float* out   = probs + (size_t)BATCH*HEADS*SEQ*SEQ;

    float *cq,*ck,*cv,*cwq,*cwk,*cwv,*cwo;
    float *gq, *gk, *gv, *gctx, *gpm, *gps, *gm, *gi;
    cudaGetSymbolAddress((void**)&cq,  g_cq);
    cudaGetSymbolAddress((void**)&ck,  g_ck);
    cudaGetSymbolAddress((void**)&cv,  g_cv);
    cudaGetSymbolAddress((void**)&cwq, g_cwq);
    cudaGetSymbolAddress((void**)&cwk, g_cwk);
    cudaGetSymbolAddress((void**)&cwv, g_cwv);
    cudaGetSymbolAddress((void**)&cwo, g_cwo);
    cudaGetSymbolAddress((void**)&gq,  g_q);
    cudaGetSymbolAddress((void**)&gk,  g_k);
    cudaGetSymbolAddress((void**)&gv,  g_v);
    cudaGetSymbolAddress((void**)&gctx, g_ctx);
    cudaGetSymbolAddress((void**)&gpm, g_pmax);
    cudaGetSymbolAddress((void**)&gps, g_psum);
    cudaGetSymbolAddress((void**)&gm,  g_m);
    cudaGetSymbolAddress((void**)&gi,  g_inv);

    const int SM_PROJ  = 18432 * 4;
    const int SM_SCORE = 17408 * 4;
    const int SM_NCTX  = 26368 * 4;
    cudaFuncSetAttribute(proj_gemm<true>,  cudaFuncAttributeMaxDynamicSharedMemorySize, SM_PROJ);
    cudaFuncSetAttribute(proj_gemm<false>, cudaFuncAttributeMaxDynamicSharedMemorySize, SM_PROJ);
    cudaFuncSetAttribute(scores_stats, cudaFuncAttributeMaxDynamicSharedMemorySize, SM_SCORE);
    cudaFuncSetAttribute(norm_ctx,     cudaFuncAttributeMaxDynamicSharedMemorySize, SM_NCTX);

    const int NBIG = (BATCH*SEQ*DMODEL)/4;   // float4 count
    const int NW   = (DMODEL*DMODEL)/4;

    // 0) tf32 pre-rounding of inputs & weights
    cvt_pass<<<dim3(148,3), 256>>>(Q, cq, NBIG, K_, ck, NBIG, V, cv, NBIG, V, cv, 0);
    cvt_pass<<<dim3(64,4),  256>>>(Wq, cwq, NW, Wk, cwk, NW, Wv, cwv, NW, Wo, cwo, NW);

    // 1) Q,K,V projections (write tf32-rounded)
    proj_gemm<true><<<dim3(8,32,3), 256, SM_PROJ>>>(cq, ck, cv, cwq, cwk, cwv, bq, bk, bv, gq, gk, gv);

    // 2) scores (raw, scaled) + per-tile row stats
    scores_stats<<<dim3(16,16,32), 256, SM_SCORE>>>(gq, gk, probs, gpm, gps);

    // 3) per-row (max, 1/sum)
    reduce_stats<<<dim3(NROWS/256), 256>>>(gpm, gps, gm, gi);

    // 4) normalize probs in place + ctx = probs @ v (ctx tf32-rounded)
    norm_ctx<<<dim3(16,32), 256, SM_NCTX>>>(probs, gv, gm, gi, gctx);

    // 5) output projection (exact fp32 out)
    proj_gemm<false><<<dim3(8,32,1), 256, SM_PROJ>>>(gctx, gctx, gctx, cwo, cwo, cwo, bo, bo, bo, out, out, out);
}

// round 5
// speedup vs baseline: 1.0021x; 1.0021x over previous
#include <cuda_runtime.h>
#include <math.h>
#include <stdint.h>

#define BATCH 2
#define SEQ 2048
#define DMODEL 1024
#define HEADS 16
#define DK 64
#define NROWS (BATCH*HEADS*SEQ)
#define NTILES 16

// tf32-rounded copies of inputs
static __device__ float g_cq[BATCH*SEQ*DMODEL];
static __device__ float g_ck[BATCH*SEQ*DMODEL];
static __device__ float g_cv[BATCH*SEQ*DMODEL];
static __device__ float g_cwq[DMODEL*DMODEL];
static __device__ float g_cwk[DMODEL*DMODEL];
static __device__ float g_cwv[DMODEL*DMODEL];
static __device__ float g_cwo[DMODEL*DMODEL];
// Projected scratch (tf32-rounded), [B,S,D] layout
static __device__ float g_q[BATCH*SEQ*DMODEL];
static __device__ float g_k[BATCH*SEQ*DMODEL];
static __device__ float g_v[BATCH*SEQ*DMODEL];
static __device__ float g_ctx[BATCH*SEQ*DMODEL];
// softmax stats
static __device__ float g_pmax[NROWS*NTILES];
static __device__ float g_psum[NROWS*NTILES];
static __device__ float g_corr[NROWS*NTILES];

__device__ __forceinline__ float to_tf32(float x) {
    float y;
    asm("cvt.rna.tf32.f32 %0, %1;" : "=f"(y) : "f"(x));
    return y;
}
__device__ __forceinline__ void mma8(float* d, const uint32_t* a, const uint32_t* b) {
    asm volatile(
        "mma.sync.aligned.m16n8k8.row.col.f32.tf32.tf32.f32 "
        "{%0,%1,%2,%3}, {%4,%5,%6,%7}, {%8,%9}, {%0,%1,%2,%3};\n"
        : "+f"(d[0]), "+f"(d[1]), "+f"(d[2]), "+f"(d[3])
        : "r"(a[0]), "r"(a[1]), "r"(a[2]), "r"(a[3]),
          "r"(b[0]), "r"(b[1]));
}
__device__ __forceinline__ void cp16(uint32_t dst_smem, const void* src) {
    asm volatile("cp.async.cg.shared.global [%0], [%1], 16;\n" :: "r"(dst_smem), "l"(src));
}
__device__ __forceinline__ void cp_commit() { asm volatile("cp.async.commit_group;\n"); }
template<int N> __device__ __forceinline__ void cp_wait() {
    asm volatile("cp.async.wait_group %0;\n" :: "n"(N));
}

// ---------------------------------------------------------------------------
__global__ void __launch_bounds__(256)
cvt_pass(const float* s0, float* d0, int n0,
         const float* s1, float* d1, int n1,
         const float* s2, float* d2, int n2,
         const float* s3, float* d3, int n3)
{
    const int z = blockIdx.y;
    const float* s = (z==0)?s0:((z==1)?s1:((z==2)?s2:s3));
    float*       d = (z==0)?d0:((z==1)?d1:((z==2)?d2:d3));
    const int    n = (z==0)?n0:((z==1)?n1:((z==2)?n2:n3));
    for (int i = blockIdx.x*256 + threadIdx.x; i < n; i += gridDim.x*256) {
        float4 x = ((const float4*)s)[i];
        x.x = to_tf32(x.x); x.y = to_tf32(x.y);
        x.z = to_tf32(x.z); x.w = to_tf32(x.w);
        ((float4*)d)[i] = x;
    }
}

// ---------------------------------------------------------------------------
// Projection GEMM: C[4096,1024] = A @ W^T + bias, z selects triple.
// ---------------------------------------------------------------------------
template<bool CVT_OUT>
__global__ void __launch_bounds__(256, 2)
proj_gemm(const float* __restrict__ A0, const float* __restrict__ A1, const float* __restrict__ A2,
          const float* __restrict__ W0, const float* __restrict__ W1, const float* __restrict__ W2,
          const float* __restrict__ B0, const float* __restrict__ B1, const float* __restrict__ B2,
          float* __restrict__ C0, float* __restrict__ C1, float* __restrict__ C2)
{
    extern __shared__ __align__(16) float sm[];
    const int tid = threadIdx.x;
    const int z = blockIdx.z;
    const float* A    = (z==0) ? A0 : ((z==1) ? A1 : A2);
    const float* W    = (z==0) ? W0 : ((z==1) ? W1 : W2);
    const float* bias = (z==0) ? B0 : ((z==1) ? B1 : B2);
    float*       C    = (z==0) ? C0 : ((z==1) ? C1 : C2);
    const int tileN = blockIdx.x * 128;
    const int tileM = blockIdx.y * 128;

    const int warp = tid >> 5, lane = tid & 31, gid = lane >> 2, tig = lane & 3;
    const int wM = (warp & 1) * 64, wN = (warp >> 1) * 32;
    const uint32_t smb = (uint32_t)__cvta_generic_to_shared(sm);

    float acc[4][4][4];
    #pragma unroll
    for (int i=0;i<4;++i)
        #pragma unroll
        for (int j=0;j<4;++j)
            #pragma unroll
            for (int r=0;r<4;++r) acc[i][j][r]=0.f;

    #pragma unroll
    for (int i=0;i<4;++i) {
        int e = tid + i*256, m = e>>3, kq = e&7;
        cp16(smb + (uint32_t)((m*36 + kq*4)*4),          A + (size_t)(tileM+m)*1024 + kq*4);
        cp16(smb + (uint32_t)((9216 + m*36 + kq*4)*4),   W + (size_t)(tileN+m)*1024 + kq*4);
    }
    cp_commit();

    for (int it = 0; it < 32; ++it) {
        const int cur = it & 1;
        if (it < 31) {
            const int nb = cur ^ 1;
            const int k0 = (it+1)*32;
            #pragma unroll
            for (int i=0;i<4;++i) {
                int e = tid + i*256, m = e>>3, kq = e&7;
                cp16(smb + (uint32_t)((nb*4608 + m*36 + kq*4)*4),        A + (size_t)(tileM+m)*1024 + k0 + kq*4);
                cp16(smb + (uint32_t)((9216 + nb*4608 + m*36 + kq*4)*4), W + (size_t)(tileN+m)*1024 + k0 + kq*4);
            }
            cp_commit();
            cp_wait<1>();
        } else {
            cp_wait<0>();
        }
        __syncthreads();

        const float* As = sm + cur*4608;
        const float* Ws = sm + 9216 + cur*4608;
        #pragma unroll
        for (int ks = 0; ks < 32; ks += 8) {
            uint32_t af[4][4], bf[4][2];
            #pragma unroll
            for (int mi=0;mi<4;++mi) {
                const int m0 = wM + mi*16;
                af[mi][0] = __float_as_uint(As[(m0+gid  )*36 + ks+tig  ]);
                af[mi][1] = __float_as_uint(As[(m0+gid+8)*36 + ks+tig  ]);
                af[mi][2] = __float_as_uint(As[(m0+gid  )*36 + ks+tig+4]);
                af[mi][3] = __float_as_uint(As[(m0+gid+8)*36 + ks+tig+4]);
            }
            #pragma unroll
            for (int ni=0;ni<4;++ni) {
                const int n0 = wN + ni*8;
                bf[ni][0] = __float_as_uint(Ws[(n0+gid)*36 + ks+tig  ]);
                bf[ni][1] = __float_as_uint(Ws[(n0+gid)*36 + ks+tig+4]);
            }
            #pragma unroll
            for (int mi=0;mi<4;++mi)
                #pragma unroll
                for (int ni=0;ni<4;++ni)
                    mma8(acc[mi][ni], af[mi], bf[ni]);
        }
        __syncthreads();
    }

    #pragma unroll
    for (int mi=0;mi<4;++mi) {
        const int r0 = tileM + wM + mi*16 + gid;
        #pragma unroll
        for (int ni=0;ni<4;++ni) {
            const int c0 = tileN + wN + ni*8 + tig*2;
            const float b0 = bias[c0], b1 = bias[c0+1];
            float v0 = acc[mi][ni][0]+b0, v1 = acc[mi][ni][1]+b1;
            float v2 = acc[mi][ni][2]+b0, v3 = acc[mi][ni][3]+b1;
            if (CVT_OUT) {
                v0 = to_tf32(v0); v1 = to_tf32(v1);
                v2 = to_tf32(v2); v3 = to_tf32(v3);
            }
            *(float2*)(C + (size_t)r0*1024 + c0)     = make_float2(v0, v1);
            *(float2*)(C + (size_t)(r0+8)*1024 + c0) = make_float2(v2, v3);
        }
    }
}

// ---------------------------------------------------------------------------
// Scores -> EXP values + per-tile row stats.
// Writes e = exp(s*scale - M_tile_row) to probs region; (M_tile, sum_e) to stats.
// ---------------------------------------------------------------------------
__global__ void __launch_bounds__(256, 2)
scores_stats(const float* __restrict__ q, const float* __restrict__ kmat,
             float* __restrict__ probs, float* __restrict__ pmax, float* __restrict__ psum)
{
    extern __shared__ __align__(16) float sm[];
    const int tid = threadIdx.x;
    const int ntile = blockIdx.x, rowtile = blockIdx.y, z = blockIdx.z;
    const int b = z >> 4, h = z & 15;

    const float* Qp = q    + ((size_t)b*SEQ + rowtile*128)*DMODEL + h*DK;
    const float* Kp = kmat + ((size_t)b*SEQ + ntile*128)*DMODEL + h*DK;
    const uint32_t smb = (uint32_t)__cvta_generic_to_shared(sm);

    #pragma unroll
    for (int i=0;i<8;++i) {
        int e = tid + i*256, m = e>>4, kq = e&15;
        cp16(smb + (uint32_t)((m*68 + kq*4)*4),          Qp + (size_t)m*1024 + kq*4);
        cp16(smb + (uint32_t)((8704 + m*68 + kq*4)*4),   Kp + (size_t)m*1024 + kq*4);
    }
    cp_commit(); cp_wait<0>();
    __syncthreads();

    const int warp = tid >> 5, lane = tid & 31, gid = lane >> 2, tig = lane & 3;
    const int wM = (warp & 1) * 64, wN = (warp >> 1) * 32, warp_n = warp >> 1;

    float acc[4][4][4];
    #pragma unroll
    for (int i=0;i<4;++i)
        #pragma unroll
        for (int j=0;j<4;++j)
            #pragma unroll
            for (int r=0;r<4;++r) acc[i][j][r]=0.f;

    const float* Qs = sm;
    const float* Ks = sm + 8704;
    #pragma unroll
    for (int ks = 0; ks < 64; ks += 8) {
        uint32_t af[4][4], bf[4][2];
        #pragma unroll
        for (int mi=0;mi<4;++mi) {
            const int m0 = wM + mi*16;
            af[mi][0] = __float_as_uint(Qs[(m0+gid  )*68 + ks+tig  ]);
            af[mi][1] = __float_as_uint(Qs[(m0+gid+8)*68 + ks+tig  ]);
            af[mi][2] = __float_as_uint(Qs[(m0+gid  )*68 + ks+tig+4]);
            af[mi][3] = __float_as_uint(Qs[(m0+gid+8)*68 + ks+tig+4]);
        }
        #pragma unroll
        for (int ni=0;ni<4;++ni) {
            const int n0 = wN + ni*8;
            bf[ni][0] = __float_as_uint(Ks[(n0+gid)*68 + ks+tig  ]);
            bf[ni][1] = __float_as_uint(Ks[(n0+gid)*68 + ks+tig+4]);
        }
        #pragma unroll
        for (int mi=0;mi<4;++mi)
            #pragma unroll
            for (int ni=0;ni<4;++ni)
                mma8(acc[mi][ni], af[mi], bf[ni]);
    }

    #pragma unroll
    for (int mi=0;mi<4;++mi)
        #pragma unroll
        for (int ni=0;ni<4;++ni)
            #pragma unroll
            for (int r=0;r<4;++r) acc[mi][ni][r] *= 0.125f;

    // --- tile-global row max: warp-local then cross-warp ---
    float* redf = sm;          // [4][128]
    float* Mrow = sm + 512;    // [128]
    float rm[4][2];
    #pragma unroll
    for (int mi=0;mi<4;++mi) {
        #pragma unroll
        for (int hf=0;hf<2;++hf) {
            float mx = -1e30f;
            #pragma unroll
            for (int ni=0;ni<4;++ni)
                mx = fmaxf(mx, fmaxf(acc[mi][ni][hf*2], acc[mi][ni][hf*2+1]));
            mx = fmaxf(mx, __shfl_xor_sync(0xffffffffu, mx, 1));
            mx = fmaxf(mx, __shfl_xor_sync(0xffffffffu, mx, 2));
            rm[mi][hf] = mx;
        }
    }
    __syncthreads();   // done with Qs/Ks
    if (tig == 0) {
        #pragma unroll
        for (int mi=0;mi<4;++mi)
            #pragma unroll
            for (int hf=0;hf<2;++hf)
                redf[warp_n*128 + wM + mi*16 + gid + hf*8] = rm[mi][hf];
    }
    __syncthreads();
    if (tid < 128) {
        float M = fmaxf(fmaxf(redf[tid], redf[128+tid]), fmaxf(redf[256+tid], redf[384+tid]));
        Mrow[tid] = M;
    }
    __syncthreads();

    // --- exp with tile-global max; overwrite acc with e; accumulate sums ---
    float rs[4][2];
    #pragma unroll
    for (int mi=0;mi<4;++mi) {
        #pragma unroll
        for (int hf=0;hf<2;++hf) {
            const float M = Mrow[wM + mi*16 + gid + hf*8];
            float s = 0.f;
            #pragma unroll
            for (int ni=0;ni<4;++ni) {
                float e0 = __expf(acc[mi][ni][hf*2]   - M);
                float e1 = __expf(acc[mi][ni][hf*2+1] - M);
                acc[mi][ni][hf*2]   = e0;
                acc[mi][ni][hf*2+1] = e1;
                s += e0 + e1;
            }
            s += __shfl_xor_sync(0xffffffffu, s, 1);
            s += __shfl_xor_sync(0xffffffffu, s, 2);
            rs[mi][hf] = s;
        }
    }
    if (tig == 0) {
        #pragma unroll
        for (int mi=0;mi<4;++mi)
            #pragma unroll
            for (int hf=0;hf<2;++hf)
                redf[warp_n*128 + wM + mi*16 + gid + hf*8] = rs[mi][hf];
    }
    __syncthreads();
    if (tid < 128) {
        float S = redf[tid] + redf[128+tid] + redf[256+tid] + redf[384+tid];
        const size_t grow = (size_t)z*SEQ + rowtile*128 + tid;
        pmax[grow*NTILES + ntile] = Mrow[tid];
        psum[grow*NTILES + ntile] = S;
    }

    // write e values
    float* Cp = probs + (size_t)z*SEQ*SEQ;
    #pragma unroll
    for (int mi=0;mi<4;++mi) {
        const int r0 = rowtile*128 + wM + mi*16 + gid;
        #pragma unroll
        for (int ni=0;ni<4;++ni) {
            const int c0 = ntile*128 + wN + ni*8 + tig*2;
            *(float2*)(Cp + (size_t)r0*SEQ + c0)     = make_float2(acc[mi][ni][0], acc[mi][ni][1]);
            *(float2*)(Cp + (size_t)(r0+8)*SEQ + c0) = make_float2(acc[mi][ni][2], acc[mi][ni][3]);
        }
    }
}

// ---------------------------------------------------------------------------
// Reduce per-tile stats -> per-(row,tile) correction exp(M_t - M)/S_global
// ---------------------------------------------------------------------------
__global__ void __launch_bounds__(256)
reduce_stats(const float* __restrict__ pmax, const float* __restrict__ psum,
             float* __restrict__ corr)
{
    const int r = blockIdx.x * 256 + threadIdx.x;
    float mx[NTILES], sx[NTILES];
    #pragma unroll
    for (int t=0;t<NTILES;++t) { mx[t]=pmax[(size_t)r*NTILES+t]; sx[t]=psum[(size_t)r*NTILES+t]; }
    float M = -1e30f;
    #pragma unroll
    for (int t=0;t<NTILES;++t) M = fmaxf(M, mx[t]);
    float S = 0.f;
    float cf[NTILES];
    #pragma unroll
    for (int t=0;t<NTILES;++t) { cf[t] = __expf(mx[t]-M); S += sx[t]*cf[t]; }
    const float inv = 1.f/S;
    #pragma unroll
    for (int t=0;t<NTILES;++t) corr[(size_t)r*NTILES+t] = cf[t]*inv;
}

// ---------------------------------------------------------------------------
// Fused normalize (p = e * corr, no exp) + ctx accumulate.
// smem (words): Ps[128][132] at 0, Vs[128][72] at 16896, corr[16][128] at 26112.
// ---------------------------------------------------------------------------
__global__ void __launch_bounds__(256, 2)
norm_ctx(float* __restrict__ probs, const float* __restrict__ v,
         const float* __restrict__ gcorr, float* __restrict__ ctx)
{
    extern __shared__ __align__(16) float sm[];
    float* Ps = sm;
    float* Vs = sm + 16896;
    float* Cs = sm + 26112;   // [nt][row]

    const int tid = threadIdx.x, rowtile = blockIdx.x, z = blockIdx.y;
    const int b = z >> 4, h = z & 15;
    const size_t grow0 = (size_t)z*SEQ + rowtile*128;

    // load all 16x128 correction factors, transposed to [nt][row]
    #pragma unroll
    for (int i=0;i<8;++i) {
        const int e = tid + i*256;           // e = row*16 + nt
        Cs[(e & 15)*128 + (e >> 4)] = gcorr[grow0*NTILES + e];
    }

    const int warp = tid >> 5, lane = tid & 31, gid = lane >> 2, tig = lane & 3;
    const int m0 = warp * 16;
    const uint32_t smb = (uint32_t)__cvta_generic_to_shared(sm);

    const float* Vp0 = v + (size_t)b*SEQ*DMODEL + h*DK;
    float* P0 = probs + (size_t)z*SEQ*SEQ + (size_t)(rowtile*128)*SEQ;

    float acc[8][4];
    #pragma unroll
    for (int i=0;i<8;++i)
        #pragma unroll
        for (int r=0;r<4;++r) acc[i][r]=0.f;

    __syncthreads();

    for (int nt = 0; nt < 16; ++nt) {
        #pragma unroll
        for (int i=0;i<8;++i) {
            int e = tid + i*256, r = e>>4, kq = e&15;
            cp16(smb + (uint32_t)((16896 + r*72 + kq*4)*4),
                 Vp0 + (size_t)(nt*128+r)*1024 + kq*4);
        }
        cp_commit();

        // normalize: p = e * corr (row-broadcast), write back + stash tf32
        const float* Crow = Cs + nt*128;
        #pragma unroll 4
        for (int j=0;j<16;++j) {
            const int e = tid + j*256, row = e>>5, c4 = e&31;
            float4* gp = (float4*)(P0 + (size_t)row*SEQ + nt*128 + c4*4);
            float4 x = *gp;
            const float cr = Crow[row];
            x.x *= cr; x.y *= cr; x.z *= cr; x.w *= cr;
            *gp = x;
            float4 t;
            t.x = to_tf32(x.x); t.y = to_tf32(x.y);
            t.z = to_tf32(x.z); t.w = to_tf32(x.w);
            *(float4*)(Ps + row*132 + c4*4) = t;
        }
        cp_wait<0>();
        __syncthreads();

        #pragma unroll 4
        for (int ks = 0; ks < 128; ks += 8) {
            uint32_t af[4], bf[8][2];
            af[0] = __float_as_uint(Ps[(m0+gid  )*132 + ks+tig  ]);
            af[1] = __float_as_uint(Ps[(m0+gid+8)*132 + ks+tig  ]);
            af[2] = __float_as_uint(Ps[(m0+gid  )*132 + ks+tig+4]);
            af[3] = __float_as_uint(Ps[(m0+gid+8)*132 + ks+tig+4]);
            #pragma unroll
            for (int ni=0;ni<8;++ni) {
                const int n0 = ni*8;
                bf[ni][0] = __float_as_uint(Vs[(ks+tig  )*72 + n0+gid]);
                bf[ni][1] = __float_as_uint(Vs[(ks+tig+4)*72 + n0+gid]);
            }
            #pragma unroll
            for (int ni=0;ni<8;++ni)
                mma8(acc[ni], af, bf[ni]);
        }
        __syncthreads();
    }

    float* Cp = ctx + ((size_t)b*SEQ + rowtile*128)*DMODEL + h*DK;
    #pragma unroll
    for (int ni=0;ni<8;++ni) {
        const int c0 = ni*8 + tig*2;
        *(float2*)(Cp + (size_t)(m0+gid)*1024 + c0)
            = make_float2(to_tf32(acc[ni][0]), to_tf32(acc[ni][1]));
        *(float2*)(Cp + (size_t)(m0+gid+8)*1024 + c0)
            = make_float2(to_tf32(acc[ni][2]), to_tf32(acc[ni][3]));
    }
}

// ---------------------------------------------------------------------------
extern "C" void kernel_launch(void* const* d_in, const int* in_sizes, int n_in,
                              void* d_out, int out_size)
{
    const float* Q  = (const float*)d_in[0];
    const float* K_ = (const float*)d_in[1];
    const float* V  = (const float*)d_in[2];
    const float* Wq = (const float*)d_in[3];
    const float* bq = (const float*)d_in[4];
    const float* Wk = (const float*)d_in[5];
    const float* bk = (const float*)d_in[6];
    const float* Wv = (const float*)d_in[7];
    const float* bv = (const float*)d_in[8];
    const float* Wo = (const float*)d_in[9];
    const float* bo = (const float*)d_in[10];

    float* probs = (float*)d_out;
    float* out   = probs + (size_t)BATCH*HEADS*SEQ*SEQ;

    float *cq,*ck,*cv,*cwq,*cwk,*cwv,*cwo;
    float *gq, *gk, *gv, *gctx, *gpm, *gps, *gc;
    cudaGetSymbolAddress((void**)&cq,  g_cq);
    cudaGetSymbolAddress((void**)&ck,  g_ck);
    cudaGetSymbolAddress((void**)&cv,  g_cv);
    cudaGetSymbolAddress((void**)&cwq, g_cwq);
    cudaGetSymbolAddress((void**)&cwk, g_cwk);
    cudaGetSymbolAddress((void**)&cwv, g_cwv);
    cudaGetSymbolAddress((void**)&cwo, g_cwo);
    cudaGetSymbolAddress((void**)&gq,  g_q);
    cudaGetSymbolAddress((void**)&gk,  g_k);
    cudaGetSymbolAddress((void**)&gv,  g_v);
    cudaGetSymbolAddress((void**)&gctx, g_ctx);
    cudaGetSymbolAddress((void**)&gpm, g_pmax);
    cudaGetSymbolAddress((void**)&gps, g_psum);
    cudaGetSymbolAddress((void**)&gc,  g_corr);

    const int SM_PROJ  = 18432 * 4;
    const int SM_SCORE = 17408 * 4;
    const int SM_NCTX  = 28160 * 4;   // Ps + Vs + corr
    cudaFuncSetAttribute(proj_gemm<true>,  cudaFuncAttributeMaxDynamicSharedMemorySize, SM_PROJ);
    cudaFuncSetAttribute(proj_gemm<false>, cudaFuncAttributeMaxDynamicSharedMemorySize, SM_PROJ);
    cudaFuncSetAttribute(scores_stats, cudaFuncAttributeMaxDynamicSharedMemorySize, SM_SCORE);
    cudaFuncSetAttribute(norm_ctx,     cudaFuncAttributeMaxDynamicSharedMemorySize, SM_NCTX);

    const int NBIG = (BATCH*SEQ*DMODEL)/4;
    const int NW   = (DMODEL*DMODEL)/4;

    // 0) tf32 pre-rounding
    cvt_pass<<<dim3(148,3), 256>>>(Q, cq, NBIG, K_, ck, NBIG, V, cv, NBIG, V, cv, 0);
    cvt_pass<<<dim3(64,4),  256>>>(Wq, cwq, NW, Wk, cwk, NW, Wv, cwv, NW, Wo, cwo, NW);

    // 1) Q,K,V projections
    proj_gemm<true><<<dim3(8,32,3), 256, SM_PROJ>>>(cq, ck, cv, cwq, cwk, cwv, bq, bk, bv, gq, gk, gv);

    // 2) scores -> exp values + per-tile stats
    scores_stats<<<dim3(16,16,32), 256, SM_SCORE>>>(gq, gk, probs, gpm, gps);

    // 3) per-(row,tile) correction factors
    reduce_stats<<<dim3(NROWS/256), 256>>>(gpm, gps, gc);

    // 4) normalize probs in place (mul only) + ctx = probs @ v
    norm_ctx<<<dim3(16,32), 256, SM_NCTX>>>(probs, gv, gc, gctx);

    // 5) output projection
    proj_gemm<false><<<dim3(8,32,1), 256, SM_PROJ>>>(gctx, gctx, gctx, cwo, cwo, cwo, bo, bo, bo, out, out, out);
}

// round 6
// speedup vs baseline: 1.1847x; 1.1823x over previous
#include <cuda_runtime.h>
#include <math.h>
#include <stdint.h>

#define BATCH 2
#define SEQ 2048
#define DMODEL 1024
#define HEADS 16
#define DK 64
#define NROWS (BATCH*HEADS*SEQ)
#define NTILES 16

// tf32-rounded copies of inputs
static __device__ float g_cq[BATCH*SEQ*DMODEL];
static __device__ float g_ck[BATCH*SEQ*DMODEL];
static __device__ float g_cv[BATCH*SEQ*DMODEL];
static __device__ float g_cwq[DMODEL*DMODEL];
static __device__ float g_cwk[DMODEL*DMODEL];
static __device__ float g_cwv[DMODEL*DMODEL];
static __device__ float g_cwo[DMODEL*DMODEL];
// Projected scratch (tf32-rounded), [B,S,D] layout
static __device__ float g_q[BATCH*SEQ*DMODEL];
static __device__ float g_k[BATCH*SEQ*DMODEL];
static __device__ float g_v[BATCH*SEQ*DMODEL];
static __device__ float g_ctx[BATCH*SEQ*DMODEL];
// softmax stats
static __device__ float g_pmax[NROWS*NTILES];
static __device__ float g_psum[NROWS*NTILES];
static __device__ float g_corr[NROWS*NTILES];

__device__ __forceinline__ float to_tf32(float x) {
    float y;
    asm("cvt.rna.tf32.f32 %0, %1;" : "=f"(y) : "f"(x));
    return y;
}
__device__ __forceinline__ void mma8(float* d, const uint32_t* a, const uint32_t* b) {
    asm volatile(
        "mma.sync.aligned.m16n8k8.row.col.f32.tf32.tf32.f32 "
        "{%0,%1,%2,%3}, {%4,%5,%6,%7}, {%8,%9}, {%0,%1,%2,%3};\n"
        : "+f"(d[0]), "+f"(d[1]), "+f"(d[2]), "+f"(d[3])
        : "r"(a[0]), "r"(a[1]), "r"(a[2]), "r"(a[3]),
          "r"(b[0]), "r"(b[1]));
}
__device__ __forceinline__ void cp16(uint32_t dst_smem, const void* src) {
    asm volatile("cp.async.cg.shared.global [%0], [%1], 16;\n" :: "r"(dst_smem), "l"(src));
}
__device__ __forceinline__ void cp_commit() { asm volatile("cp.async.commit_group;\n"); }
template<int N> __device__ __forceinline__ void cp_wait() {
    asm volatile("cp.async.wait_group %0;\n" :: "n"(N));
}

// ---------------------------------------------------------------------------
__global__ void __launch_bounds__(256)
cvt_pass(const float* s0, float* d0, int n0,
         const float* s1, float* d1, int n1,
         const float* s2, float* d2, int n2,
         const float* s3, float* d3, int n3)
{
    const int z = blockIdx.y;
    const float* s = (z==0)?s0:((z==1)?s1:((z==2)?s2:s3));
    float*       d = (z==0)?d0:((z==1)?d1:((z==2)?d2:d3));
    const int    n = (z==0)?n0:((z==1)?n1:((z==2)?n2:n3));
    for (int i = blockIdx.x*256 + threadIdx.x; i < n; i += gridDim.x*256) {
        float4 x = ((const float4*)s)[i];
        x.x = to_tf32(x.x); x.y = to_tf32(x.y);
        x.z = to_tf32(x.z); x.w = to_tf32(x.w);
        ((float4*)d)[i] = x;
    }
}

// ---------------------------------------------------------------------------
// Projection GEMM: C[4096,1024] = A @ W^T + bias, z selects triple.
// ---------------------------------------------------------------------------
template<bool CVT_OUT>
__global__ void __launch_bounds__(256, 2)
proj_gemm(const float* __restrict__ A0, const float* __restrict__ A1, const float* __restrict__ A2,
          const float* __restrict__ W0, const float* __restrict__ W1, const float* __restrict__ W2,
          const float* __restrict__ B0, const float* __restrict__ B1, const float* __restrict__ B2,
          float* __restrict__ C0, float* __restrict__ C1, float* __restrict__ C2)
{
    extern __shared__ __align__(16) float sm[];
    const int tid = threadIdx.x;
    const int z = blockIdx.z;
    const float* A    = (z==0) ? A0 : ((z==1) ? A1 : A2);
    const float* W    = (z==0) ? W0 : ((z==1) ? W1 : W2);
    const float* bias = (z==0) ? B0 : ((z==1) ? B1 : B2);
    float*       C    = (z==0) ? C0 : ((z==1) ? C1 : C2);
    const int tileN = blockIdx.x * 128;
    const int tileM = blockIdx.y * 128;

    const int warp = tid >> 5, lane = tid & 31, gid = lane >> 2, tig = lane & 3;
    const int wM = (warp & 1) * 64, wN = (warp >> 1) * 32;
    const uint32_t smb = (uint32_t)__cvta_generic_to_shared(sm);

    float acc[4][4][4];
    #pragma unroll
    for (int i=0;i<4;++i)
        #pragma unroll
        for (int j=0;j<4;++j)
            #pragma unroll
            for (int r=0;r<4;++r) acc[i][j][r]=0.f;

    #pragma unroll
    for (int i=0;i<4;++i) {
        int e = tid + i*256, m = e>>3, kq = e&7;
        cp16(smb + (uint32_t)((m*36 + kq*4)*4),          A + (size_t)(tileM+m)*1024 + kq*4);
        cp16(smb + (uint32_t)((9216 + m*36 + kq*4)*4),   W + (size_t)(tileN+m)*1024 + kq*4);
    }
    cp_commit();

    for (int it = 0; it < 32; ++it) {
        const int cur = it & 1;
        if (it < 31) {
            const int nb = cur ^ 1;
            const int k0 = (it+1)*32;
            #pragma unroll
            for (int i=0;i<4;++i) {
                int e = tid + i*256, m = e>>3, kq = e&7;
                cp16(smb + (uint32_t)((nb*4608 + m*36 + kq*4)*4),        A + (size_t)(tileM+m)*1024 + k0 + kq*4);
                cp16(smb + (uint32_t)((9216 + nb*4608 + m*36 + kq*4)*4), W + (size_t)(tileN+m)*1024 + k0 + kq*4);
            }
            cp_commit();
            cp_wait<1>();
        } else {
            cp_wait<0>();
        }
        __syncthreads();

        const float* As = sm + cur*4608;
        const float* Ws = sm + 9216 + cur*4608;
        #pragma unroll
        for (int ks = 0; ks < 32; ks += 8) {
            uint32_t af[4][4], bf[4][2];
            #pragma unroll
            for (int mi=0;mi<4;++mi) {
                const int m0 = wM + mi*16;
                af[mi][0] = __float_as_uint(As[(m0+gid  )*36 + ks+tig  ]);
                af[mi][1] = __float_as_uint(As[(m0+gid+8)*36 + ks+tig  ]);
                af[mi][2] = __float_as_uint(As[(m0+gid  )*36 + ks+tig+4]);
                af[mi][3] = __float_as_uint(As[(m0+gid+8)*36 + ks+tig+4]);
            }
            #pragma unroll
            for (int ni=0;ni<4;++ni) {
                const int n0 = wN + ni*8;
                bf[ni][0] = __float_as_uint(Ws[(n0+gid)*36 + ks+tig  ]);
                bf[ni][1] = __float_as_uint(Ws[(n0+gid)*36 + ks+tig+4]);
            }
            #pragma unroll
            for (int mi=0;mi<4;++mi)
                #pragma unroll
                for (int ni=0;ni<4;++ni)
                    mma8(acc[mi][ni], af[mi], bf[ni]);
        }
        __syncthreads();
    }

    #pragma unroll
    for (int mi=0;mi<4;++mi) {
        const int r0 = tileM + wM + mi*16 + gid;
        #pragma unroll
        for (int ni=0;ni<4;++ni) {
            const int c0 = tileN + wN + ni*8 + tig*2;
            const float b0 = bias[c0], b1 = bias[c0+1];
            float v0 = acc[mi][ni][0]+b0, v1 = acc[mi][ni][1]+b1;
            float v2 = acc[mi][ni][2]+b0, v3 = acc[mi][ni][3]+b1;
            if (CVT_OUT) {
                v0 = to_tf32(v0); v1 = to_tf32(v1);
                v2 = to_tf32(v2); v3 = to_tf32(v3);
            }
            *(float2*)(C + (size_t)r0*1024 + c0)     = make_float2(v0, v1);
            *(float2*)(C + (size_t)(r0+8)*1024 + c0) = make_float2(v2, v3);
        }
    }
}

// ---------------------------------------------------------------------------
// Scores -> EXP values + per-tile row stats.
// Writes e = exp(s*scale - M_tile_row) to probs region; (M_tile, sum_e) to stats.
// ---------------------------------------------------------------------------
__global__ void __launch_bounds__(256, 2)
scores_stats(const float* __restrict__ q, const float* __restrict__ kmat,
             float* __restrict__ probs, float* __restrict__ pmax, float* __restrict__ psum)
{
    extern __shared__ __align__(16) float sm[];
    const int tid = threadIdx.x;
    const int ntile = blockIdx.x, rowtile = blockIdx.y, z = blockIdx.z;
    const int b = z >> 4, h = z & 15;

    const float* Qp = q    + ((size_t)b*SEQ + rowtile*128)*DMODEL + h*DK;
    const float* Kp = kmat + ((size_t)b*SEQ + ntile*128)*DMODEL + h*DK;
    const uint32_t smb = (uint32_t)__cvta_generic_to_shared(sm);

    #pragma unroll
    for (int i=0;i<8;++i) {
        int e = tid + i*256, m = e>>4, kq = e&15;
        cp16(smb + (uint32_t)((m*68 + kq*4)*4),          Qp + (size_t)m*1024 + kq*4);
        cp16(smb + (uint32_t)((8704 + m*68 + kq*4)*4),   Kp + (size_t)m*1024 + kq*4);
    }
    cp_commit(); cp_wait<0>();
    __syncthreads();

    const int warp = tid >> 5, lane = tid & 31, gid = lane >> 2, tig = lane & 3;
    const int wM = (warp & 1) * 64, wN = (warp >> 1) * 32, warp_n = warp >> 1;

    float acc[4][4][4];
    #pragma unroll
    for (int i=0;i<4;++i)
        #pragma unroll
        for (int j=0;j<4;++j)
            #pragma unroll
            for (int r=0;r<4;++r) acc[i][j][r]=0.f;

    const float* Qs = sm;
    const float* Ks = sm + 8704;
    #pragma unroll
    for (int ks = 0; ks < 64; ks += 8) {
        uint32_t af[4][4], bf[4][2];
        #pragma unroll
        for (int mi=0;mi<4;++mi) {
            const int m0 = wM + mi*16;
            af[mi][0] = __float_as_uint(Qs[(m0+gid  )*68 + ks+tig  ]);
            af[mi][1] = __float_as_uint(Qs[(m0+gid+8)*68 + ks+tig  ]);
            af[mi][2] = __float_as_uint(Qs[(m0+gid  )*68 + ks+tig+4]);
            af[mi][3] = __float_as_uint(Qs[(m0+gid+8)*68 + ks+tig+4]);
        }
        #pragma unroll
        for (int ni=0;ni<4;++ni) {
            const int n0 = wN + ni*8;
            bf[ni][0] = __float_as_uint(Ks[(n0+gid)*68 + ks+tig  ]);
            bf[ni][1] = __float_as_uint(Ks[(n0+gid)*68 + ks+tig+4]);
        }
        #pragma unroll
        for (int mi=0;mi<4;++mi)
            #pragma unroll
            for (int ni=0;ni<4;++ni)
                mma8(acc[mi][ni], af[mi], bf[ni]);
    }

    #pragma unroll
    for (int mi=0;mi<4;++mi)
        #pragma unroll
        for (int ni=0;ni<4;++ni)
            #pragma unroll
            for (int r=0;r<4;++r) acc[mi][ni][r] *= 0.125f;

    float* redf = sm;
    float* Mrow = sm + 512;
    float rm[4][2];
    #pragma unroll
    for (int mi=0;mi<4;++mi) {
        #pragma unroll
        for (int hf=0;hf<2;++hf) {
            float mx = -1e30f;
            #pragma unroll
            for (int ni=0;ni<4;++ni)
                mx = fmaxf(mx, fmaxf(acc[mi][ni][hf*2], acc[mi][ni][hf*2+1]));
            mx = fmaxf(mx, __shfl_xor_sync(0xffffffffu, mx, 1));
            mx = fmaxf(mx, __shfl_xor_sync(0xffffffffu, mx, 2));
            rm[mi][hf] = mx;
        }
    }
    __syncthreads();
    if (tig == 0) {
        #pragma unroll
        for (int mi=0;mi<4;++mi)
            #pragma unroll
            for (int hf=0;hf<2;++hf)
                redf[warp_n*128 + wM + mi*16 + gid + hf*8] = rm[mi][hf];
    }
    __syncthreads();
    if (tid < 128) {
        float M = fmaxf(fmaxf(redf[tid], redf[128+tid]), fmaxf(redf[256+tid], redf[384+tid]));
        Mrow[tid] = M;
    }
    __syncthreads();

    float rs[4][2];
    #pragma unroll
    for (int mi=0;mi<4;++mi) {
        #pragma unroll
        for (int hf=0;hf<2;++hf) {
            const float M = Mrow[wM + mi*16 + gid + hf*8];
            float s = 0.f;
            #pragma unroll
            for (int ni=0;ni<4;++ni) {
                float e0 = __expf(acc[mi][ni][hf*2]   - M);
                float e1 = __expf(acc[mi][ni][hf*2+1] - M);
                acc[mi][ni][hf*2]   = e0;
                acc[mi][ni][hf*2+1] = e1;
                s += e0 + e1;
            }
            s += __shfl_xor_sync(0xffffffffu, s, 1);
            s += __shfl_xor_sync(0xffffffffu, s, 2);
            rs[mi][hf] = s;
        }
    }
    if (tig == 0) {
        #pragma unroll
        for (int mi=0;mi<4;++mi)
            #pragma unroll
            for (int hf=0;hf<2;++hf)
                redf[warp_n*128 + wM + mi*16 + gid + hf*8] = rs[mi][hf];
    }
    __syncthreads();
    if (tid < 128) {
        float S = redf[tid] + redf[128+tid] + redf[256+tid] + redf[384+tid];
        const size_t grow = (size_t)z*SEQ + rowtile*128 + tid;
        pmax[grow*NTILES + ntile] = Mrow[tid];
        psum[grow*NTILES + ntile] = S;
    }

    float* Cp = probs + (size_t)z*SEQ*SEQ;
    #pragma unroll
    for (int mi=0;mi<4;++mi) {
        const int r0 = rowtile*128 + wM + mi*16 + gid;
        #pragma unroll
        for (int ni=0;ni<4;++ni) {
            const int c0 = ntile*128 + wN + ni*8 + tig*2;
            *(float2*)(Cp + (size_t)r0*SEQ + c0)     = make_float2(acc[mi][ni][0], acc[mi][ni][1]);
            *(float2*)(Cp + (size_t)(r0+8)*SEQ + c0) = make_float2(acc[mi][ni][2], acc[mi][ni][3]);
        }
    }
}

// ---------------------------------------------------------------------------
__global__ void __launch_bounds__(256)
reduce_stats(const float* __restrict__ pmax, const float* __restrict__ psum,
             float* __restrict__ corr)
{
    const int r = blockIdx.x * 256 + threadIdx.x;
    float mx[NTILES], sx[NTILES];
    #pragma unroll
    for (int t=0;t<NTILES;++t) { mx[t]=pmax[(size_t)r*NTILES+t]; sx[t]=psum[(size_t)r*NTILES+t]; }
    float M = -1e30f;
    #pragma unroll
    for (int t=0;t<NTILES;++t) M = fmaxf(M, mx[t]);
    float S = 0.f;
    float cf[NTILES];
    #pragma unroll
    for (int t=0;t<NTILES;++t) { cf[t] = __expf(mx[t]-M); S += sx[t]*cf[t]; }
    const float inv = 1.f/S;
    #pragma unroll
    for (int t=0;t<NTILES;++t) corr[(size_t)r*NTILES+t] = cf[t]*inv;
}

// ---------------------------------------------------------------------------
// Pipelined normalize + ctx.
// smem (words): Es[128][132]=0, Ps[128][132]=16896, Vs[2][128][72]=33792,
// corr[16][128]=52224. Total 54272 words = 217088 B, occ 1.
// Per nt: wait loads -> normalize Es->(probs STG, Ps tf32) -> sync ->
// cp.async Es(nt+1)+V(nt+1) -> mma(Ps, Vs[buf]) overlapped with loads.
// ---------------------------------------------------------------------------
__global__ void __launch_bounds__(256, 1)
norm_ctx(float* __restrict__ probs, const float* __restrict__ v,
         const float* __restrict__ gcorr, float* __restrict__ ctx)
{
    extern __shared__ __align__(16) float sm[];
    float* Es = sm;
    float* Ps = sm + 16896;
    float* Vs = sm + 33792;
    float* Cs = sm + 52224;

    const int tid = threadIdx.x, rowtile = blockIdx.x, z = blockIdx.y;
    const int b = z >> 4, h = z & 15;
    const size_t grow0 = (size_t)z*SEQ + rowtile*128;

    #pragma unroll
    for (int i=0;i<8;++i) {
        const int e = tid + i*256;            // e = row*16 + nt
        Cs[(e & 15)*128 + (e >> 4)] = gcorr[grow0*NTILES + e];
    }

    const int warp = tid >> 5, lane = tid & 31, gid = lane >> 2, tig = lane & 3;
    const int m0 = warp * 16;
    const uint32_t smb = (uint32_t)__cvta_generic_to_shared(sm);

    const float* Vp0 = v + (size_t)b*SEQ*DMODEL + h*DK;
    float* P0 = probs + (size_t)z*SEQ*SEQ + (size_t)(rowtile*128)*SEQ;

    float acc[8][4];
    #pragma unroll
    for (int i=0;i<8;++i)
        #pragma unroll
        for (int r=0;r<4;++r) acc[i][r]=0.f;

    // prologue: load Es(0) + V(0)
    #pragma unroll
    for (int i=0;i<16;++i) {
        int e = tid + i*256, row = e>>5, c4 = e&31;
        cp16(smb + (uint32_t)((row*132 + c4*4)*4), P0 + (size_t)row*SEQ + c4*4);
    }
    #pragma unroll
    for (int i=0;i<8;++i) {
        int e = tid + i*256, r = e>>4, kq = e&15;
        cp16(smb + (uint32_t)((33792 + r*72 + kq*4)*4), Vp0 + (size_t)r*1024 + kq*4);
    }
    cp_commit();

    for (int nt = 0; nt < 16; ++nt) {
        const int buf = nt & 1;
        cp_wait<0>();
        __syncthreads();   // loads landed; all warps done with prior mma (Ps free)

        // normalize: p = e * corr; STG normalized probs; STS tf32 -> Ps
        const float* Crow = Cs + nt*128;
        #pragma unroll 4
        for (int j=0;j<16;++j) {
            const int e = tid + j*256, row = e>>5, c4 = e&31;
            float4 x = *(const float4*)(Es + row*132 + c4*4);
            const float cr = Crow[row];
            x.x *= cr; x.y *= cr; x.z *= cr; x.w *= cr;
            *(float4*)(P0 + (size_t)row*SEQ + nt*128 + c4*4) = x;
            float4 t;
            t.x = to_tf32(x.x); t.y = to_tf32(x.y);
            t.z = to_tf32(x.z); t.w = to_tf32(x.w);
            *(float4*)(Ps + row*132 + c4*4) = t;
        }
        __syncthreads();   // Es consumed, Ps ready

        if (nt < 15) {     // prefetch next tile during mma
            #pragma unroll
            for (int i=0;i<16;++i) {
                int e = tid + i*256, row = e>>5, c4 = e&31;
                cp16(smb + (uint32_t)((row*132 + c4*4)*4),
                     P0 + (size_t)row*SEQ + (nt+1)*128 + c4*4);
            }
            #pragma unroll
            for (int i=0;i<8;++i) {
                int e = tid + i*256, r = e>>4, kq = e&15;
                cp16(smb + (uint32_t)((33792 + (buf^1)*9216 + r*72 + kq*4)*4),
                     Vp0 + (size_t)((nt+1)*128+r)*1024 + kq*4);
            }
            cp_commit();
        }

        const float* Vb = Vs + buf*9216;
        #pragma unroll 4
        for (int ks = 0; ks < 128; ks += 8) {
            uint32_t af[4], bf[8][2];
            af[0] = __float_as_uint(Ps[(m0+gid  )*132 + ks+tig  ]);
            af[1] = __float_as_uint(Ps[(m0+gid+8)*132 + ks+tig  ]);
            af[2] = __float_as_uint(Ps[(m0+gid  )*132 + ks+tig+4]);
            af[3] = __float_as_uint(Ps[(m0+gid+8)*132 + ks+tig+4]);
            #pragma unroll
            for (int ni=0;ni<8;++ni) {
                const int n0 = ni*8;
                bf[ni][0] = __float_as_uint(Vb[(ks+tig  )*72 + n0+gid]);
                bf[ni][1] = __float_as_uint(Vb[(ks+tig+4)*72 + n0+gid]);
            }
            #pragma unroll
            for (int ni=0;ni<8;++ni)
                mma8(acc[ni], af, bf[ni]);
        }
        // no trailing sync: loop-top sync orders Ps overwrite vs mma readers
    }

    float* Cp = ctx + ((size_t)b*SEQ + rowtile*128)*DMODEL + h*DK;
    #pragma unroll
    for (int ni=0;ni<8;++ni) {
        const int c0 = ni*8 + tig*2;
        *(float2*)(Cp + (size_t)(m0+gid)*1024 + c0)
            = make_float2(to_tf32(acc[ni][0]), to_tf32(acc[ni][1]));
        *(float2*)(Cp + (size_t)(m0+gid+8)*1024 + c0)
            = make_float2(to_tf32(acc[ni][2]), to_tf32(acc[ni][3]));
    }
}

// ---------------------------------------------------------------------------
extern "C" void kernel_launch(void* const* d_in, const int* in_sizes, int n_in,
                              void* d_out, int out_size)
{
    const float* Q  = (const float*)d_in[0];
    const float* K_ = (const float*)d_in[1];
    const float* V  = (const float*)d_in[2];
    const float* Wq = (const float*)d_in[3];
    const float* bq = (const float*)d_in[4];
    const float* Wk = (const float*)d_in[5];
    const float* bk = (const float*)d_in[6];
    const float* Wv = (const float*)d_in[7];
    const float* bv = (const float*)d_in[8];
    const float* Wo = (const float*)d_in[9];
    const float* bo = (const float*)d_in[10];

    float* probs = (float*)d_out;
    float* out   = probs + (size_t)BATCH*HEADS*SEQ*SEQ;

    float *cq,*ck,*cv,*cwq,*cwk,*cwv,*cwo;
    float *gq, *gk, *gv, *gctx, *gpm, *gps, *gc;
    cudaGetSymbolAddress((void**)&cq,  g_cq);
    cudaGetSymbolAddress((void**)&ck,  g_ck);
    cudaGetSymbolAddress((void**)&cv,  g_cv);
    cudaGetSymbolAddress((void**)&cwq, g_cwq);
    cudaGetSymbolAddress((void**)&cwk, g_cwk);
    cudaGetSymbolAddress((void**)&cwv, g_cwv);
    cudaGetSymbolAddress((void**)&cwo, g_cwo);
    cudaGetSymbolAddress((void**)&gq,  g_q);
    cudaGetSymbolAddress((void**)&gk,  g_k);
    cudaGetSymbolAddress((void**)&gv,  g_v);
    cudaGetSymbolAddress((void**)&gctx, g_ctx);
    cudaGetSymbolAddress((void**)&gpm, g_pmax);
    cudaGetSymbolAddress((void**)&gps, g_psum);
    cudaGetSymbolAddress((void**)&gc,  g_corr);

    const int SM_PROJ  = 18432 * 4;
    const int SM_SCORE = 17408 * 4;
    const int SM_NCTX  = 54272 * 4;   // Es + Ps + 2*Vs + corr = 217088 B
    cudaFuncSetAttribute(proj_gemm<true>,  cudaFuncAttributeMaxDynamicSharedMemorySize, SM_PROJ);
    cudaFuncSetAttribute(proj_gemm<false>, cudaFuncAttributeMaxDynamicSharedMemorySize, SM_PROJ);
    cudaFuncSetAttribute(scores_stats, cudaFuncAttributeMaxDynamicSharedMemorySize, SM_SCORE);
    cudaFuncSetAttribute(norm_ctx,     cudaFuncAttributeMaxDynamicSharedMemorySize, SM_NCTX);

    const int NBIG = (BATCH*SEQ*DMODEL)/4;
    const int NW   = (DMODEL*DMODEL)/4;

    // 0) tf32 pre-rounding
    cvt_pass<<<dim3(148,3), 256>>>(Q, cq, NBIG, K_, ck, NBIG, V, cv, NBIG, V, cv, 0);
    cvt_pass<<<dim3(64,4),  256>>>(Wq, cwq, NW, Wk, cwk, NW, Wv, cwv, NW, Wo, cwo, NW);

    // 1) Q,K,V projections
    proj_gemm<true><<<dim3(8,32,3), 256, SM_PROJ>>>(cq, ck, cv, cwq, cwk, cwv, bq, bk, bv, gq, gk, gv);

    // 2) scores -> exp values + per-tile stats
    scores_stats<<<dim3(16,16,32), 256, SM_SCORE>>>(gq, gk, probs, gpm, gps);

    // 3) per-(row,tile) correction factors
    reduce_stats<<<dim3(NROWS/256), 256>>>(gpm, gps, gc);

    // 4) pipelined normalize + ctx
    norm_ctx<<<dim3(16,32), 256, SM_NCTX>>>(probs, gv, gc, gctx);

    // 5) output projection
    proj_gemm<false><<<dim3(8,32,1), 256, SM_PROJ>>>(gctx, gctx, gctx, cwo, cwo, cwo, bo, bo, bo, out, out, out);
}

// round 7
// speedup vs baseline: 1.2262x; 1.0350x over previous
#include <cuda_runtime.h>
#include <math.h>
#include <stdint.h>

#define BATCH 2
#define SEQ 2048
#define DMODEL 1024
#define HEADS 16
#define DK 64
#define NROWS (BATCH*HEADS*SEQ)
#define NTILES 16

// tf32-rounded copies of inputs
static __device__ float g_cq[BATCH*SEQ*DMODEL];
static __device__ float g_ck[BATCH*SEQ*DMODEL];
static __device__ float g_cv[BATCH*SEQ*DMODEL];
static __device__ float g_cwq[DMODEL*DMODEL];
static __device__ float g_cwk[DMODEL*DMODEL];
static __device__ float g_cwv[DMODEL*DMODEL];
static __device__ float g_cwo[DMODEL*DMODEL];
// Projected scratch (tf32-rounded), [B,S,D] layout
static __device__ float g_q[BATCH*SEQ*DMODEL];
static __device__ float g_k[BATCH*SEQ*DMODEL];
static __device__ float g_v[BATCH*SEQ*DMODEL];
static __device__ float g_ctx[BATCH*SEQ*DMODEL];
// softmax stats (no-max softmax: only sums needed)
static __device__ float g_psum[NROWS*NTILES];
static __device__ float g_inv[NROWS];

__device__ __forceinline__ float to_tf32(float x) {
    float y;
    asm("cvt.rna.tf32.f32 %0, %1;" : "=f"(y) : "f"(x));
    return y;
}
__device__ __forceinline__ void mma8(float* d, const uint32_t* a, const uint32_t* b) {
    asm volatile(
        "mma.sync.aligned.m16n8k8.row.col.f32.tf32.tf32.f32 "
        "{%0,%1,%2,%3}, {%4,%5,%6,%7}, {%8,%9}, {%0,%1,%2,%3};\n"
        : "+f"(d[0]), "+f"(d[1]), "+f"(d[2]), "+f"(d[3])
        : "r"(a[0]), "r"(a[1]), "r"(a[2]), "r"(a[3]),
          "r"(b[0]), "r"(b[1]));
}
__device__ __forceinline__ void cp16(uint32_t dst_smem, const void* src) {
    asm volatile("cp.async.cg.shared.global [%0], [%1], 16;\n" :: "r"(dst_smem), "l"(src));
}
__device__ __forceinline__ void cp_commit() { asm volatile("cp.async.commit_group;\n"); }
template<int N> __device__ __forceinline__ void cp_wait() {
    asm volatile("cp.async.wait_group %0;\n" :: "n"(N));
}

// ---------------------------------------------------------------------------
__global__ void __launch_bounds__(256)
cvt_pass(const float* s0, float* d0, int n0,
         const float* s1, float* d1, int n1,
         const float* s2, float* d2, int n2,
         const float* s3, float* d3, int n3)
{
    const int z = blockIdx.y;
    const float* s = (z==0)?s0:((z==1)?s1:((z==2)?s2:s3));
    float*       d = (z==0)?d0:((z==1)?d1:((z==2)?d2:d3));
    const int    n = (z==0)?n0:((z==1)?n1:((z==2)?n2:n3));
    for (int i = blockIdx.x*256 + threadIdx.x; i < n; i += gridDim.x*256) {
        float4 x = ((const float4*)s)[i];
        x.x = to_tf32(x.x); x.y = to_tf32(x.y);
        x.z = to_tf32(x.z); x.w = to_tf32(x.w);
        ((float4*)d)[i] = x;
    }
}

// ---------------------------------------------------------------------------
// Projection GEMM: C[4096,1024] = A @ W^T + bias, z selects triple.
// ---------------------------------------------------------------------------
template<bool CVT_OUT>
__global__ void __launch_bounds__(256, 2)
proj_gemm(const float* __restrict__ A0, const float* __restrict__ A1, const float* __restrict__ A2,
          const float* __restrict__ W0, const float* __restrict__ W1, const float* __restrict__ W2,
          const float* __restrict__ B0, const float* __restrict__ B1, const float* __restrict__ B2,
          float* __restrict__ C0, float* __restrict__ C1, float* __restrict__ C2)
{
    extern __shared__ __align__(16) float sm[];
    const int tid = threadIdx.x;
    const int z = blockIdx.z;
    const float* A    = (z==0) ? A0 : ((z==1) ? A1 : A2);
    const float* W    = (z==0) ? W0 : ((z==1) ? W1 : W2);
    const float* bias = (z==0) ? B0 : ((z==1) ? B1 : B2);
    float*       C    = (z==0) ? C0 : ((z==1) ? C1 : C2);
    const int tileN = blockIdx.x * 128;
    const int tileM = blockIdx.y * 128;

    const int warp = tid >> 5, lane = tid & 31, gid = lane >> 2, tig = lane & 3;
    const int wM = (warp & 1) * 64, wN = (warp >> 1) * 32;
    const uint32_t smb = (uint32_t)__cvta_generic_to_shared(sm);

    float acc[4][4][4];
    #pragma unroll
    for (int i=0;i<4;++i)
        #pragma unroll
        for (int j=0;j<4;++j)
            #pragma unroll
            for (int r=0;r<4;++r) acc[i][j][r]=0.f;

    #pragma unroll
    for (int i=0;i<4;++i) {
        int e = tid + i*256, m = e>>3, kq = e&7;
        cp16(smb + (uint32_t)((m*36 + kq*4)*4),          A + (size_t)(tileM+m)*1024 + kq*4);
        cp16(smb + (uint32_t)((9216 + m*36 + kq*4)*4),   W + (size_t)(tileN+m)*1024 + kq*4);
    }
    cp_commit();

    for (int it = 0; it < 32; ++it) {
        const int cur = it & 1;
        if (it < 31) {
            const int nb = cur ^ 1;
            const int k0 = (it+1)*32;
            #pragma unroll
            for (int i=0;i<4;++i) {
                int e = tid + i*256, m = e>>3, kq = e&7;
                cp16(smb + (uint32_t)((nb*4608 + m*36 + kq*4)*4),        A + (size_t)(tileM+m)*1024 + k0 + kq*4);
                cp16(smb + (uint32_t)((9216 + nb*4608 + m*36 + kq*4)*4), W + (size_t)(tileN+m)*1024 + k0 + kq*4);
            }
            cp_commit();
            cp_wait<1>();
        } else {
            cp_wait<0>();
        }
        __syncthreads();

        const float* As = sm + cur*4608;
        const float* Ws = sm + 9216 + cur*4608;
        #pragma unroll
        for (int ks = 0; ks < 32; ks += 8) {
            uint32_t af[4][4], bf[4][2];
            #pragma unroll
            for (int mi=0;mi<4;++mi) {
                const int m0 = wM + mi*16;
                af[mi][0] = __float_as_uint(As[(m0+gid  )*36 + ks+tig  ]);
                af[mi][1] = __float_as_uint(As[(m0+gid+8)*36 + ks+tig  ]);
                af[mi][2] = __float_as_uint(As[(m0+gid  )*36 + ks+tig+4]);
                af[mi][3] = __float_as_uint(As[(m0+gid+8)*36 + ks+tig+4]);
            }
            #pragma unroll
            for (int ni=0;ni<4;++ni) {
                const int n0 = wN + ni*8;
                bf[ni][0] = __float_as_uint(Ws[(n0+gid)*36 + ks+tig  ]);
                bf[ni][1] = __float_as_uint(Ws[(n0+gid)*36 + ks+tig+4]);
            }
            #pragma unroll
            for (int mi=0;mi<4;++mi)
                #pragma unroll
                for (int ni=0;ni<4;++ni)
                    mma8(acc[mi][ni], af[mi], bf[ni]);
        }
        __syncthreads();
    }

    #pragma unroll
    for (int mi=0;mi<4;++mi) {
        const int r0 = tileM + wM + mi*16 + gid;
        #pragma unroll
        for (int ni=0;ni<4;++ni) {
            const int c0 = tileN + wN + ni*8 + tig*2;
            const float b0 = bias[c0], b1 = bias[c0+1];
            float v0 = acc[mi][ni][0]+b0, v1 = acc[mi][ni][1]+b1;
            float v2 = acc[mi][ni][2]+b0, v3 = acc[mi][ni][3]+b1;
            if (CVT_OUT) {
                v0 = to_tf32(v0); v1 = to_tf32(v1);
                v2 = to_tf32(v2); v3 = to_tf32(v3);
            }
            *(float2*)(C + (size_t)r0*1024 + c0)     = make_float2(v0, v1);
            *(float2*)(C + (size_t)(r0+8)*1024 + c0) = make_float2(v2, v3);
        }
    }
}

// ---------------------------------------------------------------------------
// Scores -> e = exp(s/8) (no max subtraction) + per-tile row sums.
// ---------------------------------------------------------------------------
__global__ void __launch_bounds__(256, 2)
scores_stats(const float* __restrict__ q, const float* __restrict__ kmat,
             float* __restrict__ probs, float* __restrict__ psum)
{
    extern __shared__ __align__(16) float sm[];
    const int tid = threadIdx.x;
    const int ntile = blockIdx.x, rowtile = blockIdx.y, z = blockIdx.z;
    const int b = z >> 4, h = z & 15;

    const float* Qp = q    + ((size_t)b*SEQ + rowtile*128)*DMODEL + h*DK;
    const float* Kp = kmat + ((size_t)b*SEQ + ntile*128)*DMODEL + h*DK;
    const uint32_t smb = (uint32_t)__cvta_generic_to_shared(sm);

    #pragma unroll
    for (int i=0;i<8;++i) {
        int e = tid + i*256, m = e>>4, kq = e&15;
        cp16(smb + (uint32_t)((m*68 + kq*4)*4),          Qp + (size_t)m*1024 + kq*4);
        cp16(smb + (uint32_t)((8704 + m*68 + kq*4)*4),   Kp + (size_t)m*1024 + kq*4);
    }
    cp_commit(); cp_wait<0>();
    __syncthreads();

    const int warp = tid >> 5, lane = tid & 31, gid = lane >> 2, tig = lane & 3;
    const int wM = (warp & 1) * 64, wN = (warp >> 1) * 32, warp_n = warp >> 1;

    float acc[4][4][4];
    #pragma unroll
    for (int i=0;i<4;++i)
        #pragma unroll
        for (int j=0;j<4;++j)
            #pragma unroll
            for (int r=0;r<4;++r) acc[i][j][r]=0.f;

    const float* Qs = sm;
    const float* Ks = sm + 8704;
    #pragma unroll
    for (int ks = 0; ks < 64; ks += 8) {
        uint32_t af[4][4], bf[4][2];
        #pragma unroll
        for (int mi=0;mi<4;++mi) {
            const int m0 = wM + mi*16;
            af[mi][0] = __float_as_uint(Qs[(m0+gid  )*68 + ks+tig  ]);
            af[mi][1] = __float_as_uint(Qs[(m0+gid+8)*68 + ks+tig  ]);
            af[mi][2] = __float_as_uint(Qs[(m0+gid  )*68 + ks+tig+4]);
            af[mi][3] = __float_as_uint(Qs[(m0+gid+8)*68 + ks+tig+4]);
        }
        #pragma unroll
        for (int ni=0;ni<4;++ni) {
            const int n0 = wN + ni*8;
            bf[ni][0] = __float_as_uint(Ks[(n0+gid)*68 + ks+tig  ]);
            bf[ni][1] = __float_as_uint(Ks[(n0+gid)*68 + ks+tig+4]);
        }
        #pragma unroll
        for (int mi=0;mi<4;++mi)
            #pragma unroll
            for (int ni=0;ni<4;++ni)
                mma8(acc[mi][ni], af[mi], bf[ni]);
    }

    // e = exp(s/8), per-thread row partial sums, lane reduce (groups of 4)
    float rs[4][2];
    #pragma unroll
    for (int mi=0;mi<4;++mi) {
        #pragma unroll
        for (int hf=0;hf<2;++hf) {
            float s = 0.f;
            #pragma unroll
            for (int ni=0;ni<4;++ni) {
                float e0 = __expf(acc[mi][ni][hf*2]   * 0.125f);
                float e1 = __expf(acc[mi][ni][hf*2+1] * 0.125f);
                acc[mi][ni][hf*2]   = e0;
                acc[mi][ni][hf*2+1] = e1;
                s += e0 + e1;
            }
            s += __shfl_xor_sync(0xffffffffu, s, 1);
            s += __shfl_xor_sync(0xffffffffu, s, 2);
            rs[mi][hf] = s;
        }
    }
    __syncthreads();   // Qs/Ks done; reuse smem for reduction
    float* redf = sm;  // [4 warp_n][128 rows]
    if (tig == 0) {
        #pragma unroll
        for (int mi=0;mi<4;++mi)
            #pragma unroll
            for (int hf=0;hf<2;++hf)
                redf[warp_n*128 + wM + mi*16 + gid + hf*8] = rs[mi][hf];
    }
    __syncthreads();
    if (tid < 128) {
        float S = redf[tid] + redf[128+tid] + redf[256+tid] + redf[384+tid];
        const size_t grow = (size_t)z*SEQ + rowtile*128 + tid;
        psum[grow*NTILES + ntile] = S;
    }

    // write e values
    float* Cp = probs + (size_t)z*SEQ*SEQ;
    #pragma unroll
    for (int mi=0;mi<4;++mi) {
        const int r0 = rowtile*128 + wM + mi*16 + gid;
        #pragma unroll
        for (int ni=0;ni<4;++ni) {
            const int c0 = ntile*128 + wN + ni*8 + tig*2;
            *(float2*)(Cp + (size_t)r0*SEQ + c0)     = make_float2(acc[mi][ni][0], acc[mi][ni][1]);
            *(float2*)(Cp + (size_t)(r0+8)*SEQ + c0) = make_float2(acc[mi][ni][2], acc[mi][ni][3]);
        }
    }
}

// ---------------------------------------------------------------------------
__global__ void __launch_bounds__(256)
reduce_stats(const float* __restrict__ psum, float* __restrict__ ginv)
{
    const int r = blockIdx.x * 256 + threadIdx.x;
    float S = 0.f;
    #pragma unroll
    for (int t=0;t<NTILES;++t) S += psum[(size_t)r*NTILES+t];
    ginv[r] = 1.f/S;
}

// ---------------------------------------------------------------------------
// Normalize (p = e * inv) + ctx, 64-row tiles, occupancy 2.
// smem (words): Es[64][132]=0, Ps[64][132]=8448, Vs[128][72]=16896, inv=26112.
// Total 26176 words = 104704 B -> 2 CTAs/SM; cross-CTA overlap of load vs mma.
// ---------------------------------------------------------------------------
__global__ void __launch_bounds__(256, 2)
norm_ctx(float* __restrict__ probs, const float* __restrict__ v,
         const float* __restrict__ ginv, float* __restrict__ ctx)
{
    extern __shared__ __align__(16) float sm[];
    float* Es  = sm;
    float* Ps  = sm + 8448;
    float* Vs  = sm + 16896;
    float* smi = sm + 26112;

    const int tid = threadIdx.x, rowtile = blockIdx.x, z = blockIdx.y;
    const int b = z >> 4, h = z & 15;
    const size_t grow0 = (size_t)z*SEQ + rowtile*64;
    if (tid < 64) smi[tid] = ginv[grow0+tid];

    const int warp = tid >> 5, lane = tid & 31, gid = lane >> 2, tig = lane & 3;
    const int m0 = (warp & 3) * 16;          // 4 warps across M=64
    const int wN = (warp >> 2) * 32;         // 2 warps across N=64
    const uint32_t smb = (uint32_t)__cvta_generic_to_shared(sm);

    const float* Vp0 = v + (size_t)b*SEQ*DMODEL + h*DK;
    float* P0 = probs + (size_t)z*SEQ*SEQ + (size_t)(rowtile*64)*SEQ;

    float acc[4][4];
    #pragma unroll
    for (int i=0;i<4;++i)
        #pragma unroll
        for (int r=0;r<4;++r) acc[i][r]=0.f;

    __syncthreads();

    for (int nt = 0; nt < 16; ++nt) {
        // load e tile (64x128) + V tile (128x64)
        #pragma unroll
        for (int i=0;i<8;++i) {
            int e = tid + i*256, row = e>>5, c4 = e&31;
            cp16(smb + (uint32_t)((row*132 + c4*4)*4),
                 P0 + (size_t)row*SEQ + nt*128 + c4*4);
        }
        #pragma unroll
        for (int i=0;i<8;++i) {
            int e = tid + i*256, r = e>>4, kq = e&15;
            cp16(smb + (uint32_t)((16896 + r*72 + kq*4)*4),
                 Vp0 + (size_t)(nt*128+r)*1024 + kq*4);
        }
        cp_commit(); cp_wait<0>();
        __syncthreads();

        // normalize: p = e*inv -> STG + tf32 to Ps
        #pragma unroll 4
        for (int j=0;j<8;++j) {
            const int e = tid + j*256, row = e>>5, c4 = e&31;
            float4 x = *(const float4*)(Es + row*132 + c4*4);
            const float iv = smi[row];
            x.x *= iv; x.y *= iv; x.z *= iv; x.w *= iv;
            *(float4*)(P0 + (size_t)row*SEQ + nt*128 + c4*4) = x;
            float4 t;
            t.x = to_tf32(x.x); t.y = to_tf32(x.y);
            t.z = to_tf32(x.z); t.w = to_tf32(x.w);
            *(float4*)(Ps + row*132 + c4*4) = t;
        }
        __syncthreads();

        #pragma unroll 4
        for (int ks = 0; ks < 128; ks += 8) {
            uint32_t af[4], bf[4][2];
            af[0] = __float_as_uint(Ps[(m0+gid  )*132 + ks+tig  ]);
            af[1] = __float_as_uint(Ps[(m0+gid+8)*132 + ks+tig  ]);
            af[2] = __float_as_uint(Ps[(m0+gid  )*132 + ks+tig+4]);
            af[3] = __float_as_uint(Ps[(m0+gid+8)*132 + ks+tig+4]);
            #pragma unroll
            for (int ni=0;ni<4;++ni) {
                const int n0 = wN + ni*8;
                bf[ni][0] = __float_as_uint(Vs[(ks+tig  )*72 + n0+gid]);
                bf[ni][1] = __float_as_uint(Vs[(ks+tig+4)*72 + n0+gid]);
            }
            #pragma unroll
            for (int ni=0;ni<4;++ni)
                mma8(acc[ni], af, bf[ni]);
        }
        __syncthreads();   // all warps done with Es/Ps/Vs before next loads
    }

    float* Cp = ctx + ((size_t)b*SEQ + rowtile*64)*DMODEL + h*DK;
    #pragma unroll
    for (int ni=0;ni<4;++ni) {
        const int c0 = wN + ni*8 + tig*2;
        *(float2*)(Cp + (size_t)(m0+gid)*1024 + c0)
            = make_float2(to_tf32(acc[ni][0]), to_tf32(acc[ni][1]));
        *(float2*)(Cp + (size_t)(m0+gid+8)*1024 + c0)
            = make_float2(to_tf32(acc[ni][2]), to_tf32(acc[ni][3]));
    }
}

// ---------------------------------------------------------------------------
extern "C" void kernel_launch(void* const* d_in, const int* in_sizes, int n_in,
                              void* d_out, int out_size)
{
    const float* Q  = (const float*)d_in[0];
    const float* K_ = (const float*)d_in[1];
    const float* V  = (const float*)d_in[2];
    const float* Wq = (const float*)d_in[3];
    const float* bq = (const float*)d_in[4];
    const float* Wk = (const float*)d_in[5];
    const float* bk = (const float*)d_in[6];
    const float* Wv = (const float*)d_in[7];
    const float* bv = (const float*)d_in[8];
    const float* Wo = (const float*)d_in[9];
    const float* bo = (const float*)d_in[10];

    float* probs = (float*)d_out;
    float* out   = probs + (size_t)BATCH*HEADS*SEQ*SEQ;

    float *cq,*ck,*cv,*cwq,*cwk,*cwv,*cwo;
    float *gq, *gk, *gv, *gctx, *gps, *gi;
    cudaGetSymbolAddress((void**)&cq,  g_cq);
    cudaGetSymbolAddress((void**)&ck,  g_ck);
    cudaGetSymbolAddress((void**)&cv,  g_cv);
    cudaGetSymbolAddress((void**)&cwq, g_cwq);
    cudaGetSymbolAddress((void**)&cwk, g_cwk);
    cudaGetSymbolAddress((void**)&cwv, g_cwv);
    cudaGetSymbolAddress((void**)&cwo, g_cwo);
    cudaGetSymbolAddress((void**)&gq,  g_q);
    cudaGetSymbolAddress((void**)&gk,  g_k);
    cudaGetSymbolAddress((void**)&gv,  g_v);
    cudaGetSymbolAddress((void**)&gctx, g_ctx);
    cudaGetSymbolAddress((void**)&gps, g_psum);
    cudaGetSymbolAddress((void**)&gi,  g_inv);

    const int SM_PROJ  = 18432 * 4;
    const int SM_SCORE = 17408 * 4;
    const int SM_NCTX  = 26176 * 4;   // 104704 B -> occ 2
    cudaFuncSetAttribute(proj_gemm<true>,  cudaFuncAttributeMaxDynamicSharedMemorySize, SM_PROJ);
    cudaFuncSetAttribute(proj_gemm<false>, cudaFuncAttributeMaxDynamicSharedMemorySize, SM_PROJ);
    cudaFuncSetAttribute(scores_stats, cudaFuncAttributeMaxDynamicSharedMemorySize, SM_SCORE);
    cudaFuncSetAttribute(norm_ctx,     cudaFuncAttributeMaxDynamicSharedMemorySize, SM_NCTX);

    const int NBIG = (BATCH*SEQ*DMODEL)/4;
    const int NW   = (DMODEL*DMODEL)/4;

    // 0) tf32 pre-rounding
    cvt_pass<<<dim3(148,3), 256>>>(Q, cq, NBIG, K_, ck, NBIG, V, cv, NBIG, V, cv, 0);
    cvt_pass<<<dim3(64,4),  256>>>(Wq, cwq, NW, Wk, cwk, NW, Wv, cwv, NW, Wo, cwo, NW);

    // 1) Q,K,V projections
    proj_gemm<true><<<dim3(8,32,3), 256, SM_PROJ>>>(cq, ck, cv, cwq, cwk, cwv, bq, bk, bv, gq, gk, gv);

    // 2) scores -> e = exp(s/8) + per-tile row sums (no max)
    scores_stats<<<dim3(16,16,32), 256, SM_SCORE>>>(gq, gk, probs, gps);

    // 3) per-row 1/sum
    reduce_stats<<<dim3(NROWS/256), 256>>>(gps, gi);

    // 4) normalize + ctx (64-row tiles, occ 2)
    norm_ctx<<<dim3(32,32), 256, SM_NCTX>>>(probs, gv, gi, gctx);

    // 5) output projection
    proj_gemm<false><<<dim3(8,32,1), 256, SM_PROJ>>>(gctx, gctx, gctx, cwo, cwo, cwo, bo, bo, bo, out, out, out);
}

// round 8
// speedup vs baseline: 1.2389x; 1.0103x over previous
#include <cuda_runtime.h>
#include <math.h>
#include <stdint.h>

#define BATCH 2
#define SEQ 2048
#define DMODEL 1024
#define HEADS 16
#define DK 64
#define NROWS (BATCH*HEADS*SEQ)
#define NTILES 16

// tf32-rounded copies of inputs
static __device__ float g_cq[BATCH*SEQ*DMODEL];
static __device__ float g_ck[BATCH*SEQ*DMODEL];
static __device__ float g_cv[BATCH*SEQ*DMODEL];
static __device__ float g_cwq[DMODEL*DMODEL];
static __device__ float g_cwk[DMODEL*DMODEL];
static __device__ float g_cwv[DMODEL*DMODEL];
static __device__ float g_cwo[DMODEL*DMODEL];
// Projected scratch (tf32-rounded), [B,S,D] layout
static __device__ float g_q[BATCH*SEQ*DMODEL];
static __device__ float g_k[BATCH*SEQ*DMODEL];
static __device__ float g_v[BATCH*SEQ*DMODEL];
static __device__ float g_ctx[BATCH*SEQ*DMODEL];
// softmax stats
static __device__ float g_psum[NROWS*NTILES];
static __device__ float g_inv[NROWS];

__device__ __forceinline__ float to_tf32(float x) {
    float y;
    asm("cvt.rna.tf32.f32 %0, %1;" : "=f"(y) : "f"(x));
    return y;
}
__device__ __forceinline__ void mma8(float* d, const uint32_t* a, const uint32_t* b) {
    asm volatile(
        "mma.sync.aligned.m16n8k8.row.col.f32.tf32.tf32.f32 "
        "{%0,%1,%2,%3}, {%4,%5,%6,%7}, {%8,%9}, {%0,%1,%2,%3};\n"
        : "+f"(d[0]), "+f"(d[1]), "+f"(d[2]), "+f"(d[3])
        : "r"(a[0]), "r"(a[1]), "r"(a[2]), "r"(a[3]),
          "r"(b[0]), "r"(b[1]));
}
__device__ __forceinline__ void cp16(uint32_t dst_smem, const void* src) {
    asm volatile("cp.async.cg.shared.global [%0], [%1], 16;\n" :: "r"(dst_smem), "l"(src));
}
__device__ __forceinline__ void cp_commit() { asm volatile("cp.async.commit_group;\n"); }
template<int N> __device__ __forceinline__ void cp_wait() {
    asm volatile("cp.async.wait_group %0;\n" :: "n"(N));
}

// ---------------------------------------------------------------------------
__global__ void __launch_bounds__(256)
cvt_pass(const float* s0, float* d0, int n0,
         const float* s1, float* d1, int n1,
         const float* s2, float* d2, int n2,
         const float* s3, float* d3, int n3)
{
    const int z = blockIdx.y;
    const float* s = (z==0)?s0:((z==1)?s1:((z==2)?s2:s3));
    float*       d = (z==0)?d0:((z==1)?d1:((z==2)?d2:d3));
    const int    n = (z==0)?n0:((z==1)?n1:((z==2)?n2:n3));
    for (int i = blockIdx.x*256 + threadIdx.x; i < n; i += gridDim.x*256) {
        float4 x = ((const float4*)s)[i];
        x.x = to_tf32(x.x); x.y = to_tf32(x.y);
        x.z = to_tf32(x.z); x.w = to_tf32(x.w);
        ((float4*)d)[i] = x;
    }
}

// ---------------------------------------------------------------------------
// Projection GEMM: C[4096,1024] = A @ W^T + bias, z selects triple.
// ---------------------------------------------------------------------------
template<bool CVT_OUT>
__global__ void __launch_bounds__(256, 2)
proj_gemm(const float* __restrict__ A0, const float* __restrict__ A1, const float* __restrict__ A2,
          const float* __restrict__ W0, const float* __restrict__ W1, const float* __restrict__ W2,
          const float* __restrict__ B0, const float* __restrict__ B1, const float* __restrict__ B2,
          float* __restrict__ C0, float* __restrict__ C1, float* __restrict__ C2)
{
    extern __shared__ __align__(16) float sm[];
    const int tid = threadIdx.x;
    const int z = blockIdx.z;
    const float* A    = (z==0) ? A0 : ((z==1) ? A1 : A2);
    const float* W    = (z==0) ? W0 : ((z==1) ? W1 : W2);
    const float* bias = (z==0) ? B0 : ((z==1) ? B1 : B2);
    float*       C    = (z==0) ? C0 : ((z==1) ? C1 : C2);
    const int tileN = blockIdx.x * 128;
    const int tileM = blockIdx.y * 128;

    const int warp = tid >> 5, lane = tid & 31, gid = lane >> 2, tig = lane & 3;
    const int wM = (warp & 1) * 64, wN = (warp >> 1) * 32;
    const uint32_t smb = (uint32_t)__cvta_generic_to_shared(sm);

    float acc[4][4][4];
    #pragma unroll
    for (int i=0;i<4;++i)
        #pragma unroll
        for (int j=0;j<4;++j)
            #pragma unroll
            for (int r=0;r<4;++r) acc[i][j][r]=0.f;

    #pragma unroll
    for (int i=0;i<4;++i) {
        int e = tid + i*256, m = e>>3, kq = e&7;
        cp16(smb + (uint32_t)((m*36 + kq*4)*4),          A + (size_t)(tileM+m)*1024 + kq*4);
        cp16(smb + (uint32_t)((9216 + m*36 + kq*4)*4),   W + (size_t)(tileN+m)*1024 + kq*4);
    }
    cp_commit();

    for (int it = 0; it < 32; ++it) {
        const int cur = it & 1;
        if (it < 31) {
            const int nb = cur ^ 1;
            const int k0 = (it+1)*32;
            #pragma unroll
            for (int i=0;i<4;++i) {
                int e = tid + i*256, m = e>>3, kq = e&7;
                cp16(smb + (uint32_t)((nb*4608 + m*36 + kq*4)*4),        A + (size_t)(tileM+m)*1024 + k0 + kq*4);
                cp16(smb + (uint32_t)((9216 + nb*4608 + m*36 + kq*4)*4), W + (size_t)(tileN+m)*1024 + k0 + kq*4);
            }
            cp_commit();
            cp_wait<1>();
        } else {
            cp_wait<0>();
        }
        __syncthreads();

        const float* As = sm + cur*4608;
        const float* Ws = sm + 9216 + cur*4608;
        #pragma unroll
        for (int ks = 0; ks < 32; ks += 8) {
            uint32_t af[4][4], bf[4][2];
            #pragma unroll
            for (int mi=0;mi<4;++mi) {
                const int m0 = wM + mi*16;
                af[mi][0] = __float_as_uint(As[(m0+gid  )*36 + ks+tig  ]);
                af[mi][1] = __float_as_uint(As[(m0+gid+8)*36 + ks+tig  ]);
                af[mi][2] = __float_as_uint(As[(m0+gid  )*36 + ks+tig+4]);
                af[mi][3] = __float_as_uint(As[(m0+gid+8)*36 + ks+tig+4]);
            }
            #pragma unroll
            for (int ni=0;ni<4;++ni) {
                const int n0 = wN + ni*8;
                bf[ni][0] = __float_as_uint(Ws[(n0+gid)*36 + ks+tig  ]);
                bf[ni][1] = __float_as_uint(Ws[(n0+gid)*36 + ks+tig+4]);
            }
            #pragma unroll
            for (int mi=0;mi<4;++mi)
                #pragma unroll
                for (int ni=0;ni<4;++ni)
                    mma8(acc[mi][ni], af[mi], bf[ni]);
        }
        __syncthreads();
    }

    #pragma unroll
    for (int mi=0;mi<4;++mi) {
        const int r0 = tileM + wM + mi*16 + gid;
        #pragma unroll
        for (int ni=0;ni<4;++ni) {
            const int c0 = tileN + wN + ni*8 + tig*2;
            const float b0 = bias[c0], b1 = bias[c0+1];
            float v0 = acc[mi][ni][0]+b0, v1 = acc[mi][ni][1]+b1;
            float v2 = acc[mi][ni][2]+b0, v3 = acc[mi][ni][3]+b1;
            if (CVT_OUT) {
                v0 = to_tf32(v0); v1 = to_tf32(v1);
                v2 = to_tf32(v2); v3 = to_tf32(v3);
            }
            *(float2*)(C + (size_t)r0*1024 + c0)     = make_float2(v0, v1);
            *(float2*)(C + (size_t)(r0+8)*1024 + c0) = make_float2(v2, v3);
        }
    }
}

// ---------------------------------------------------------------------------
// Scores -> e = tf32(exp(s/8)) + per-tile row sums (no max subtraction).
// e is tf32-valued so norm_ctx can feed it to mma without conversion.
// ---------------------------------------------------------------------------
__global__ void __launch_bounds__(256, 2)
scores_stats(const float* __restrict__ q, const float* __restrict__ kmat,
             float* __restrict__ probs, float* __restrict__ psum)
{
    extern __shared__ __align__(16) float sm[];
    const int tid = threadIdx.x;
    const int ntile = blockIdx.x, rowtile = blockIdx.y, z = blockIdx.z;
    const int b = z >> 4, h = z & 15;

    const float* Qp = q    + ((size_t)b*SEQ + rowtile*128)*DMODEL + h*DK;
    const float* Kp = kmat + ((size_t)b*SEQ + ntile*128)*DMODEL + h*DK;
    const uint32_t smb = (uint32_t)__cvta_generic_to_shared(sm);

    #pragma unroll
    for (int i=0;i<8;++i) {
        int e = tid + i*256, m = e>>4, kq = e&15;
        cp16(smb + (uint32_t)((m*68 + kq*4)*4),          Qp + (size_t)m*1024 + kq*4);
        cp16(smb + (uint32_t)((8704 + m*68 + kq*4)*4),   Kp + (size_t)m*1024 + kq*4);
    }
    cp_commit(); cp_wait<0>();
    __syncthreads();

    const int warp = tid >> 5, lane = tid & 31, gid = lane >> 2, tig = lane & 3;
    const int wM = (warp & 1) * 64, wN = (warp >> 1) * 32, warp_n = warp >> 1;

    float acc[4][4][4];
    #pragma unroll
    for (int i=0;i<4;++i)
        #pragma unroll
        for (int j=0;j<4;++j)
            #pragma unroll
            for (int r=0;r<4;++r) acc[i][j][r]=0.f;

    const float* Qs = sm;
    const float* Ks = sm + 8704;
    #pragma unroll
    for (int ks = 0; ks < 64; ks += 8) {
        uint32_t af[4][4], bf[4][2];
        #pragma unroll
        for (int mi=0;mi<4;++mi) {
            const int m0 = wM + mi*16;
            af[mi][0] = __float_as_uint(Qs[(m0+gid  )*68 + ks+tig  ]);
            af[mi][1] = __float_as_uint(Qs[(m0+gid+8)*68 + ks+tig  ]);
            af[mi][2] = __float_as_uint(Qs[(m0+gid  )*68 + ks+tig+4]);
            af[mi][3] = __float_as_uint(Qs[(m0+gid+8)*68 + ks+tig+4]);
        }
        #pragma unroll
        for (int ni=0;ni<4;++ni) {
            const int n0 = wN + ni*8;
            bf[ni][0] = __float_as_uint(Ks[(n0+gid)*68 + ks+tig  ]);
            bf[ni][1] = __float_as_uint(Ks[(n0+gid)*68 + ks+tig+4]);
        }
        #pragma unroll
        for (int mi=0;mi<4;++mi)
            #pragma unroll
            for (int ni=0;ni<4;++ni)
                mma8(acc[mi][ni], af[mi], bf[ni]);
    }

    float rs[4][2];
    #pragma unroll
    for (int mi=0;mi<4;++mi) {
        #pragma unroll
        for (int hf=0;hf<2;++hf) {
            float s = 0.f;
            #pragma unroll
            for (int ni=0;ni<4;++ni) {
                float e0 = to_tf32(__expf(acc[mi][ni][hf*2]   * 0.125f));
                float e1 = to_tf32(__expf(acc[mi][ni][hf*2+1] * 0.125f));
                acc[mi][ni][hf*2]   = e0;
                acc[mi][ni][hf*2+1] = e1;
                s += e0 + e1;
            }
            s += __shfl_xor_sync(0xffffffffu, s, 1);
            s += __shfl_xor_sync(0xffffffffu, s, 2);
            rs[mi][hf] = s;
        }
    }
    __syncthreads();
    float* redf = sm;
    if (tig == 0) {
        #pragma unroll
        for (int mi=0;mi<4;++mi)
            #pragma unroll
            for (int hf=0;hf<2;++hf)
                redf[warp_n*128 + wM + mi*16 + gid + hf*8] = rs[mi][hf];
    }
    __syncthreads();
    if (tid < 128) {
        float S = redf[tid] + redf[128+tid] + redf[256+tid] + redf[384+tid];
        const size_t grow = (size_t)z*SEQ + rowtile*128 + tid;
        psum[grow*NTILES + ntile] = S;
    }

    float* Cp = probs + (size_t)z*SEQ*SEQ;
    #pragma unroll
    for (int mi=0;mi<4;++mi) {
        const int r0 = rowtile*128 + wM + mi*16 + gid;
        #pragma unroll
        for (int ni=0;ni<4;++ni) {
            const int c0 = ntile*128 + wN + ni*8 + tig*2;
            *(float2*)(Cp + (size_t)r0*SEQ + c0)     = make_float2(acc[mi][ni][0], acc[mi][ni][1]);
            *(float2*)(Cp + (size_t)(r0+8)*SEQ + c0) = make_float2(acc[mi][ni][2], acc[mi][ni][3]);
        }
    }
}

// ---------------------------------------------------------------------------
__global__ void __launch_bounds__(256)
reduce_stats(const float* __restrict__ psum, float* __restrict__ ginv)
{
    const int r = blockIdx.x * 256 + threadIdx.x;
    float S = 0.f;
    #pragma unroll
    for (int t=0;t<NTILES;++t) S += psum[(size_t)r*NTILES+t];
    ginv[r] = 1.f/S;
}

// ---------------------------------------------------------------------------
// Normalize + ctx, 64-row tiles, occ 2, Es double-buffered.
// e in memory is tf32-valued: mma reads Es raw; probs STG = e*inv (FMUL);
// ctx epilogue scales by inv[row]. No Ps staging buffer.
// smem (words): Es[2][64][132] = 0..16896, Vs[128][72] = 16896, inv[64] = 26112.
// Total 26176 words = 104704 B -> occ 2.
// ---------------------------------------------------------------------------
__global__ void __launch_bounds__(256, 2)
norm_ctx(float* __restrict__ probs, const float* __restrict__ v,
         const float* __restrict__ ginv, float* __restrict__ ctx)
{
    extern __shared__ __align__(16) float sm[];
    float* Vs  = sm + 16896;
    float* smi = sm + 26112;

    const int tid = threadIdx.x, rowtile = blockIdx.x, z = blockIdx.y;
    const int b = z >> 4, h = z & 15;
    const size_t grow0 = (size_t)z*SEQ + rowtile*64;
    if (tid < 64) smi[tid] = ginv[grow0+tid];

    const int warp = tid >> 5, lane = tid & 31, gid = lane >> 2, tig = lane & 3;
    const int m0 = (warp & 3) * 16;          // 4 warps across M=64
    const int wN = (warp >> 2) * 32;         // 2 warps across N=64
    const uint32_t smb = (uint32_t)__cvta_generic_to_shared(sm);

    const float* Vp0 = v + (size_t)b*SEQ*DMODEL + h*DK;
    float* P0 = probs + (size_t)z*SEQ*SEQ + (size_t)(rowtile*64)*SEQ;

    float acc[4][4];
    #pragma unroll
    for (int i=0;i<4;++i)
        #pragma unroll
        for (int r=0;r<4;++r) acc[i][r]=0.f;

    // prologue: Es(0) + V(0)
    #pragma unroll
    for (int i=0;i<8;++i) {
        int e = tid + i*256, row = e>>5, c4 = e&31;
        cp16(smb + (uint32_t)((row*132 + c4*4)*4), P0 + (size_t)row*SEQ + c4*4);
    }
    #pragma unroll
    for (int i=0;i<8;++i) {
        int e = tid + i*256, r = e>>4, kq = e&15;
        cp16(smb + (uint32_t)((16896 + r*72 + kq*4)*4), Vp0 + (size_t)r*1024 + kq*4);
    }
    cp_commit();

    for (int nt = 0; nt < 16; ++nt) {
        const int cur = nt & 1;
        const float* Eb = sm + cur*8448;
        cp_wait<0>();
        __syncthreads();

        // prefetch Es(nt+1) into other buffer; overlaps normalize + mma
        if (nt < 15) {
            #pragma unroll
            for (int i=0;i<8;++i) {
                int e = tid + i*256, row = e>>5, c4 = e&31;
                cp16(smb + (uint32_t)(((cur^1)*8448 + row*132 + c4*4)*4),
                     P0 + (size_t)row*SEQ + (nt+1)*128 + c4*4);
            }
            cp_commit();
        }

        // probs STG: p = e * inv (e already tf32-valued)
        #pragma unroll 4
        for (int j=0;j<8;++j) {
            const int e = tid + j*256, row = e>>5, c4 = e&31;
            float4 x = *(const float4*)(Eb + row*132 + c4*4);
            const float iv = smi[row];
            x.x *= iv; x.y *= iv; x.z *= iv; x.w *= iv;
            *(float4*)(P0 + (size_t)row*SEQ + nt*128 + c4*4) = x;
        }

        // mma: acc += e @ V (unnormalized; scaled by inv at epilogue)
        #pragma unroll 4
        for (int ks = 0; ks < 128; ks += 8) {
            uint32_t af[4], bf[4][2];
            af[0] = __float_as_uint(Eb[(m0+gid  )*132 + ks+tig  ]);
            af[1] = __float_as_uint(Eb[(m0+gid+8)*132 + ks+tig  ]);
            af[2] = __float_as_uint(Eb[(m0+gid  )*132 + ks+tig+4]);
            af[3] = __float_as_uint(Eb[(m0+gid+8)*132 + ks+tig+4]);
            #pragma unroll
            for (int ni=0;ni<4;++ni) {
                const int n0 = wN + ni*8;
                bf[ni][0] = __float_as_uint(Vs[(ks+tig  )*72 + n0+gid]);
                bf[ni][1] = __float_as_uint(Vs[(ks+tig+4)*72 + n0+gid]);
            }
            #pragma unroll
            for (int ni=0;ni<4;++ni)
                mma8(acc[ni], af, bf[ni]);
        }
        __syncthreads();   // all warps done reading Vs (and Eb) for this nt

        // load next V tile into the single V buffer (L2-resident stream)
        if (nt < 15) {
            #pragma unroll
            for (int i=0;i<8;++i) {
                int e = tid + i*256, r = e>>4, kq = e&15;
                cp16(smb + (uint32_t)((16896 + r*72 + kq*4)*4),
                     Vp0 + (size_t)((nt+1)*128+r)*1024 + kq*4);
            }
            cp_commit();
        }
    }

    // epilogue: scale by inv[row]
    float* Cp = ctx + ((size_t)b*SEQ + rowtile*64)*DMODEL + h*DK;
    #pragma unroll
    for (int ni=0;ni<4;++ni) {
        const int c0 = wN + ni*8 + tig*2;
        const float iv0 = smi[m0+gid], iv1 = smi[m0+gid+8];
        *(float2*)(Cp + (size_t)(m0+gid)*1024 + c0)
            = make_float2(to_tf32(acc[ni][0]*iv0), to_tf32(acc[ni][1]*iv0));
        *(float2*)(Cp + (size_t)(m0+gid+8)*1024 + c0)
            = make_float2(to_tf32(acc[ni][2]*iv1), to_tf32(acc[ni][3]*iv1));
    }
}

// ---------------------------------------------------------------------------
extern "C" void kernel_launch(void* const* d_in, const int* in_sizes, int n_in,
                              void* d_out, int out_size)
{
    const float* Q  = (const float*)d_in[0];
    const float* K_ = (const float*)d_in[1];
    const float* V  = (const float*)d_in[2];
    const float* Wq = (const float*)d_in[3];
    const float* bq = (const float*)d_in[4];
    const float* Wk = (const float*)d_in[5];
    const float* bk = (const float*)d_in[6];
    const float* Wv = (const float*)d_in[7];
    const float* bv = (const float*)d_in[8];
    const float* Wo = (const float*)d_in[9];
    const float* bo = (const float*)d_in[10];

    float* probs = (float*)d_out;
    float* out   = probs + (size_t)BATCH*HEADS*SEQ*SEQ;

    float *cq,*ck,*cv,*cwq,*cwk,*cwv,*cwo;
    float *gq, *gk, *gv, *gctx, *gps, *gi;
    cudaGetSymbolAddress((void**)&cq,  g_cq);
    cudaGetSymbolAddress((void**)&ck,  g_ck);
    cudaGetSymbolAddress((void**)&cv,  g_cv);
    cudaGetSymbolAddress((void**)&cwq, g_cwq);
    cudaGetSymbolAddress((void**)&cwk, g_cwk);
    cudaGetSymbolAddress((void**)&cwv, g_cwv);
    cudaGetSymbolAddress((void**)&cwo, g_cwo);
    cudaGetSymbolAddress((void**)&gq,  g_q);
    cudaGetSymbolAddress((void**)&gk,  g_k);
    cudaGetSymbolAddress((void**)&gv,  g_v);
    cudaGetSymbolAddress((void**)&gctx, g_ctx);
    cudaGetSymbolAddress((void**)&gps, g_psum);
    cudaGetSymbolAddress((void**)&gi,  g_inv);

    const int SM_PROJ  = 18432 * 4;
    const int SM_SCORE = 17408 * 4;
    const int SM_NCTX  = 26176 * 4;   // 104704 B -> occ 2
    cudaFuncSetAttribute(proj_gemm<true>,  cudaFuncAttributeMaxDynamicSharedMemorySize, SM_PROJ);
    cudaFuncSetAttribute(proj_gemm<false>, cudaFuncAttributeMaxDynamicSharedMemorySize, SM_PROJ);
    cudaFuncSetAttribute(scores_stats, cudaFuncAttributeMaxDynamicSharedMemorySize, SM_SCORE);
    cudaFuncSetAttribute(norm_ctx,     cudaFuncAttributeMaxDynamicSharedMemorySize, SM_NCTX);

    const int NBIG = (BATCH*SEQ*DMODEL)/4;
    const int NW   = (DMODEL*DMODEL)/4;

    // 0) tf32 pre-rounding
    cvt_pass<<<dim3(148,3), 256>>>(Q, cq, NBIG, K_, ck, NBIG, V, cv, NBIG, V, cv, 0);
    cvt_pass<<<dim3(64,4),  256>>>(Wq, cwq, NW, Wk, cwk, NW, Wv, cwv, NW, Wo, cwo, NW);

    // 1) Q,K,V projections
    proj_gemm<true><<<dim3(8,32,3), 256, SM_PROJ>>>(cq, ck, cv, cwq, cwk, cwv, bq, bk, bv, gq, gk, gv);

    // 2) scores -> e = tf32(exp(s/8)) + per-tile row sums
    scores_stats<<<dim3(16,16,32), 256, SM_SCORE>>>(gq, gk, probs, gps);

    // 3) per-row 1/sum
    reduce_stats<<<dim3(NROWS/256), 256>>>(gps, gi);

    // 4) normalize + ctx (Es double-buffered, inv folded into epilogue)
    norm_ctx<<<dim3(32,32), 256, SM_NCTX>>>(probs, gv, gi, gctx);

    // 5) output projection
    proj_gemm<false><<<dim3(8,32,1), 256, SM_PROJ>>>(gctx, gctx, gctx, cwo, cwo, cwo, bo, bo, bo, out, out, out);
}